// round 4
// baseline (speedup 1.0000x reference)
#include <cuda_runtime.h>
#include <math.h>

#define NPOS 4096
#define QK_SCALE 0.2041241452319315f  /* 24^-0.5 */
#define KSPLIT 4

// Scratch (device globals — no allocation allowed)
__device__ float g_buf1[576 * NPOS];            // qkv after 1x1 conv
__device__ float g_buf2[576 * NPOS];            // qkv after dw conv (q,k normalized in place)
__device__ float g_attn[192 * NPOS];            // attention output, [c][p]
__device__ float g_pacc[8 * KSPLIT * 24 * NPOS];// split-K partial acc
__device__ float g_pl[8 * KSPLIT * NPOS];       // split-K partial l

typedef unsigned long long u64t;

__device__ __forceinline__ u64t ffma2(u64t a, u64t b, u64t c) {
    u64t d;
    asm("fma.rn.f32x2 %0, %1, %2, %3;" : "=l"(d) : "l"(a), "l"(b), "l"(c));
    return d;
}
__device__ __forceinline__ u64t pack2(float lo, float hi) {
    u64t r; asm("mov.b64 %0, {%1, %2};" : "=l"(r) : "f"(lo), "f"(hi)); return r;
}
__device__ __forceinline__ float2 unpack2(u64t v) {
    float2 f; asm("mov.b64 {%0, %1}, %2;" : "=f"(f.x), "=f"(f.y) : "l"(v)); return f;
}

// exp(s) for |s| <= 0.205 via degree-4 Taylor (max rel err ~4e-7).
// All constants are immediates -> no register cost; runs on fma pipe.
__device__ __forceinline__ float exp_small(float s) {
    float t = fmaf(0.041666667f, s, 0.16666667f);  // 1/24*s + 1/6
    t = fmaf(t, s, 0.5f);
    t = fmaf(t, s, 1.0f);
    t = fmaf(t, s, 1.0f);
    return t;
}

// ---------------------------------------------------------------------------
// Pointwise (1x1) conv as GEMM: out[o][p] = sum_c w[o*IC+c] * in[c][p]
// ---------------------------------------------------------------------------
__global__ __launch_bounds__(256) void pw_conv_kernel(
    float* __restrict__ out, const float* __restrict__ in,
    const float* __restrict__ w, int IC)
{
    __shared__ __align__(16) float ws[16][65];
    __shared__ __align__(16) float xs[16][64];

    const int tid = threadIdx.x;
    const int tx = tid & 15, ty = tid >> 4;
    const int p0 = blockIdx.x * 64;
    const int o0 = blockIdx.y * 64;

    float acc[4][4] = {};

    for (int c0 = 0; c0 < IC; c0 += 16) {
        __syncthreads();
#pragma unroll
        for (int i = 0; i < 4; i++) {
            int e = tid + i * 256;
            int oo = e >> 4, ck = e & 15;
            ws[ck][oo] = w[(o0 + oo) * IC + c0 + ck];
        }
#pragma unroll
        for (int i = 0; i < 4; i++) {
            int e = tid + i * 256;
            int ck = e >> 6, pp = e & 63;
            xs[ck][pp] = in[(c0 + ck) * NPOS + p0 + pp];
        }
        __syncthreads();
#pragma unroll
        for (int ck = 0; ck < 16; ck++) {
            float4 xv = *(const float4*)&xs[ck][tx * 4];
            float w0 = ws[ck][ty * 4 + 0];
            float w1 = ws[ck][ty * 4 + 1];
            float w2 = ws[ck][ty * 4 + 2];
            float w3 = ws[ck][ty * 4 + 3];
            acc[0][0] += w0 * xv.x; acc[0][1] += w0 * xv.y; acc[0][2] += w0 * xv.z; acc[0][3] += w0 * xv.w;
            acc[1][0] += w1 * xv.x; acc[1][1] += w1 * xv.y; acc[1][2] += w1 * xv.z; acc[1][3] += w1 * xv.w;
            acc[2][0] += w2 * xv.x; acc[2][1] += w2 * xv.y; acc[2][2] += w2 * xv.z; acc[2][3] += w2 * xv.w;
            acc[3][0] += w3 * xv.x; acc[3][1] += w3 * xv.y; acc[3][2] += w3 * xv.z; acc[3][3] += w3 * xv.w;
        }
    }
#pragma unroll
    for (int i = 0; i < 4; i++)
#pragma unroll
        for (int j = 0; j < 4; j++)
            out[(o0 + ty * 4 + i) * NPOS + p0 + tx * 4 + j] = acc[i][j];
}

// ---------------------------------------------------------------------------
// Depthwise 3x3 conv, padding=1
// ---------------------------------------------------------------------------
__global__ __launch_bounds__(256) void dw_conv_kernel(
    float* __restrict__ out, const float* __restrict__ in,
    const float* __restrict__ w)
{
    const int o = blockIdx.y;
    const int p = blockIdx.x * 256 + threadIdx.x;
    const int y = p >> 6, x = p & 63;
    const float* ip = in + o * NPOS;
    const float* wp = w + o * 9;
    float acc = 0.f;
#pragma unroll
    for (int dy = 0; dy < 3; dy++) {
        int yy = y + dy - 1;
        if (yy < 0 || yy > 63) continue;
#pragma unroll
        for (int dx = 0; dx < 3; dx++) {
            int xx = x + dx - 1;
            if (xx < 0 || xx > 63) continue;
            acc += wp[dy * 3 + dx] * ip[yy * 64 + xx];
        }
    }
    out[o * NPOS + p] = acc;
}

// ---------------------------------------------------------------------------
// L2-normalize q and k along head_dim(24); fold QK_SCALE into q.
// ---------------------------------------------------------------------------
__global__ __launch_bounds__(256) void norm_kernel(float* __restrict__ qkv)
{
    const int g = blockIdx.x * 256 + threadIdx.x;
    const int t = g >> 15;
    const int rem = g & 32767;
    const int h = rem >> 12;
    const int p = rem & 4095;
    float* base = qkv + (t * 192 + h * 24) * NPOS + p;
    float ss = 0.f;
#pragma unroll
    for (int d = 0; d < 24; d++) {
        float v = base[d * NPOS];
        ss += v * v;
    }
    float inv = 1.0f / fmaxf(sqrtf(ss), 1e-12f);
    if (t == 0) inv *= QK_SCALE;
#pragma unroll
    for (int d = 0; d < 24; d++)
        base[d * NPOS] *= inv;
}

// ---------------------------------------------------------------------------
// Flash-style attention, fp32 packed-f32x2, TWO query rows per lane.
// Per key per warp: 12 LDS.128 vs ~56 fma-pipe ops -> fma-bound.
// Scores bounded (|s| <= 0.205) => exp via 4-FFMA Taylor, no MUFU, no
// max-tracking; split-K partials combine by plain addition.
// ---------------------------------------------------------------------------
__global__ __launch_bounds__(256, 2) void attn_kernel(
    float* __restrict__ pacc, float* __restrict__ pl,
    const float* __restrict__ qkv)
{
    __shared__ __align__(16) float ks[128 * 24];
    __shared__ __align__(16) float vs[128 * 24];

    const int tid   = threadIdx.x;
    const int head  = blockIdx.z;
    const int split = blockIdx.y;
    const int r0    = blockIdx.x * 512 + tid;
    const int r1    = r0 + 256;

    const float* qb = qkv + head * 24 * NPOS;
    const float* kb = qb + 192 * NPOS;
    const float* vb = kb + 192 * NPOS;

    u64t q0[12], q1[12];
#pragma unroll
    for (int i = 0; i < 12; i++) {
        q0[i] = pack2(qb[(2 * i) * NPOS + r0], qb[(2 * i + 1) * NPOS + r0]);
        q1[i] = pack2(qb[(2 * i) * NPOS + r1], qb[(2 * i + 1) * NPOS + r1]);
    }

    u64t acc0[12], acc1[12];
#pragma unroll
    for (int i = 0; i < 12; i++) { acc0[i] = 0ull; acc1[i] = 0ull; }
    float l0 = 0.f, l1 = 0.f;

    const int kbase = split * (NPOS / KSPLIT);

    for (int kt = 0; kt < (NPOS / KSPLIT) / 128; kt++) {
        const int j0 = kbase + kt * 128;
        __syncthreads();
#pragma unroll
        for (int i = 0; i < 12; i++) {
            int e = i * 256 + tid;            // 3072 elems per array
            int d = e >> 7, j = e & 127;
            ks[j * 24 + d] = kb[d * NPOS + j0 + j];
            vs[j * 24 + d] = vb[d * NPOS + j0 + j];
        }
        __syncthreads();

#pragma unroll 2
        for (int j = 0; j < 128; j++) {
            const ulonglong2* kp = (const ulonglong2*)(ks + j * 24);
            u64t sa0 = 0ull, sb0 = 0ull, sa1 = 0ull, sb1 = 0ull;
            {
                ulonglong2 t0 = kp[0], t1 = kp[1], t2 = kp[2];
                sa0 = ffma2(q0[0], t0.x, sa0);  sa1 = ffma2(q1[0], t0.x, sa1);
                sb0 = ffma2(q0[1], t0.y, sb0);  sb1 = ffma2(q1[1], t0.y, sb1);
                sa0 = ffma2(q0[2], t1.x, sa0);  sa1 = ffma2(q1[2], t1.x, sa1);
                sb0 = ffma2(q0[3], t1.y, sb0);  sb1 = ffma2(q1[3], t1.y, sb1);
                sa0 = ffma2(q0[4], t2.x, sa0);  sa1 = ffma2(q1[4], t2.x, sa1);
                sb0 = ffma2(q0[5], t2.y, sb0);  sb1 = ffma2(q1[5], t2.y, sb1);
            }
            {
                ulonglong2 t3 = kp[3], t4 = kp[4], t5 = kp[5];
                sa0 = ffma2(q0[6],  t3.x, sa0);  sa1 = ffma2(q1[6],  t3.x, sa1);
                sb0 = ffma2(q0[7],  t3.y, sb0);  sb1 = ffma2(q1[7],  t3.y, sb1);
                sa0 = ffma2(q0[8],  t4.x, sa0);  sa1 = ffma2(q1[8],  t4.x, sa1);
                sb0 = ffma2(q0[9],  t4.y, sb0);  sb1 = ffma2(q1[9],  t4.y, sb1);
                sa0 = ffma2(q0[10], t5.x, sa0);  sa1 = ffma2(q1[10], t5.x, sa1);
                sb0 = ffma2(q0[11], t5.y, sb0);  sb1 = ffma2(q1[11], t5.y, sb1);
            }

            float2 fa0 = unpack2(sa0), fb0 = unpack2(sb0);
            float2 fa1 = unpack2(sa1), fb1 = unpack2(sb1);
            float s0 = (fa0.x + fa0.y) + (fb0.x + fb0.y);
            float s1 = (fa1.x + fa1.y) + (fb1.x + fb1.y);
            float p0 = exp_small(s0);     // bounded scores — Taylor exp, fma pipe
            float p1 = exp_small(s1);
            l0 += p0;
            l1 += p1;
            u64t p20 = pack2(p0, p0);
            u64t p21 = pack2(p1, p1);

            const ulonglong2* vp = (const ulonglong2*)(vs + j * 24);
            {
                ulonglong2 t0 = vp[0], t1 = vp[1], t2 = vp[2];
                acc0[0] = ffma2(p20, t0.x, acc0[0]);  acc1[0] = ffma2(p21, t0.x, acc1[0]);
                acc0[1] = ffma2(p20, t0.y, acc0[1]);  acc1[1] = ffma2(p21, t0.y, acc1[1]);
                acc0[2] = ffma2(p20, t1.x, acc0[2]);  acc1[2] = ffma2(p21, t1.x, acc1[2]);
                acc0[3] = ffma2(p20, t1.y, acc0[3]);  acc1[3] = ffma2(p21, t1.y, acc1[3]);
                acc0[4] = ffma2(p20, t2.x, acc0[4]);  acc1[4] = ffma2(p21, t2.x, acc1[4]);
                acc0[5] = ffma2(p20, t2.y, acc0[5]);  acc1[5] = ffma2(p21, t2.y, acc1[5]);
            }
            {
                ulonglong2 t3 = vp[3], t4 = vp[4], t5 = vp[5];
                acc0[6]  = ffma2(p20, t3.x, acc0[6]);   acc1[6]  = ffma2(p21, t3.x, acc1[6]);
                acc0[7]  = ffma2(p20, t3.y, acc0[7]);   acc1[7]  = ffma2(p21, t3.y, acc1[7]);
                acc0[8]  = ffma2(p20, t4.x, acc0[8]);   acc1[8]  = ffma2(p21, t4.x, acc1[8]);
                acc0[9]  = ffma2(p20, t4.y, acc0[9]);   acc1[9]  = ffma2(p21, t4.y, acc1[9]);
                acc0[10] = ffma2(p20, t5.x, acc0[10]);  acc1[10] = ffma2(p21, t5.x, acc1[10]);
                acc0[11] = ffma2(p20, t5.y, acc0[11]);  acc1[11] = ffma2(p21, t5.y, acc1[11]);
            }
        }
    }

    // Write partials (coalesced: lanes differ by row)
    float* pa0 = pacc + ((head * KSPLIT + split) * 24) * NPOS + r0;
    float* pa1 = pacc + ((head * KSPLIT + split) * 24) * NPOS + r1;
#pragma unroll
    for (int i = 0; i < 12; i++) {
        float2 f0 = unpack2(acc0[i]);
        float2 f1 = unpack2(acc1[i]);
        pa0[(2 * i) * NPOS]     = f0.x;
        pa0[(2 * i + 1) * NPOS] = f0.y;
        pa1[(2 * i) * NPOS]     = f1.x;
        pa1[(2 * i + 1) * NPOS] = f1.y;
    }
    pl[(head * KSPLIT + split) * NPOS + r0] = l0;
    pl[(head * KSPLIT + split) * NPOS + r1] = l1;
}

// ---------------------------------------------------------------------------
// Combine split-K partials (plain sums — no max bookkeeping needed).
// ---------------------------------------------------------------------------
__global__ __launch_bounds__(256) void combine_kernel(
    float* __restrict__ out, const float* __restrict__ pacc,
    const float* __restrict__ pl)
{
    const int g = blockIdx.x * 256 + threadIdx.x;   // 32768 = 8 heads * 4096 rows
    const int head = g >> 12, row = g & 4095;
    float l = 0.f;
#pragma unroll
    for (int s = 0; s < KSPLIT; s++)
        l += pl[(head * KSPLIT + s) * NPOS + row];
    const float inv = 1.0f / l;
#pragma unroll
    for (int d = 0; d < 24; d++) {
        float a = 0.f;
#pragma unroll
        for (int s = 0; s < KSPLIT; s++)
            a += pacc[((head * KSPLIT + s) * 24 + d) * NPOS + row];
        out[(head * 24 + d) * NPOS + row] = a * inv;
    }
}

// ---------------------------------------------------------------------------
extern "C" void kernel_launch(void* const* d_in, const int* in_sizes, int n_in,
                              void* d_out, int out_size)
{
    const float* x      = (const float*)d_in[0];
    const float* w_qkv  = (const float*)d_in[1];
    const float* w_dw   = (const float*)d_in[2];
    const float* w_proj = (const float*)d_in[3];
    float* out = (float*)d_out;

    float *b1, *b2, *at, *pa, *plv;
    cudaGetSymbolAddress((void**)&b1, g_buf1);
    cudaGetSymbolAddress((void**)&b2, g_buf2);
    cudaGetSymbolAddress((void**)&at, g_attn);
    cudaGetSymbolAddress((void**)&pa, g_pacc);
    cudaGetSymbolAddress((void**)&plv, g_pl);

    pw_conv_kernel<<<dim3(NPOS / 64, 576 / 64), 256>>>(b1, x, w_qkv, 192);
    dw_conv_kernel<<<dim3(NPOS / 256, 576), 256>>>(b2, b1, w_dw);
    norm_kernel<<<256, 256>>>(b2);
    attn_kernel<<<dim3(NPOS / 512, KSPLIT, 8), 256>>>(pa, plv, b2);
    combine_kernel<<<128, 256>>>(at, pa, plv);
    pw_conv_kernel<<<dim3(NPOS / 64, 192 / 64), 256>>>(out, at, w_proj, 192);
}

// round 5
// speedup vs baseline: 1.5172x; 1.5172x over previous
#include <cuda_runtime.h>
#include <math.h>

#define NPOS 4096
#define QK_SCALE 0.2041241452319315f  /* 24^-0.5 */
#define KSPLIT 4

// Scratch (device globals — no allocation allowed)
__device__ float g_buf1[576 * NPOS];            // qkv after 1x1 conv
__device__ float g_buf2[576 * NPOS];            // qkv after dw conv (q,k normalized in place)
__device__ float g_attn[192 * NPOS];            // attention output, [c][p]
__device__ float g_pacc[8 * KSPLIT * 24 * NPOS];// split-K partial acc
__device__ float g_pl[8 * KSPLIT * NPOS];       // split-K partial l

typedef unsigned long long u64t;

__device__ __forceinline__ u64t ffma2(u64t a, u64t b, u64t c) {
    u64t d;
    asm("fma.rn.f32x2 %0, %1, %2, %3;" : "=l"(d) : "l"(a), "l"(b), "l"(c));
    return d;
}
__device__ __forceinline__ u64t fadd2(u64t a, u64t b) {
    u64t d;
    asm("add.rn.f32x2 %0, %1, %2;" : "=l"(d) : "l"(a), "l"(b));
    return d;
}
__device__ __forceinline__ u64t pack2(float lo, float hi) {
    u64t r; asm("mov.b64 %0, {%1, %2};" : "=l"(r) : "f"(lo), "f"(hi)); return r;
}
__device__ __forceinline__ float2 unpack2(u64t v) {
    float2 f; asm("mov.b64 {%0, %1}, %2;" : "=f"(f.x), "=f"(f.y) : "l"(v)); return f;
}
__device__ __forceinline__ void cp4(unsigned s, const float* g) {
    asm volatile("cp.async.ca.shared.global [%0], [%1], 4;" :: "r"(s), "l"(g));
}

// ---------------------------------------------------------------------------
// Pointwise (1x1) conv as GEMM: out[o][p] = sum_c w[o*IC+c] * in[c][p]
// ---------------------------------------------------------------------------
__global__ __launch_bounds__(256) void pw_conv_kernel(
    float* __restrict__ out, const float* __restrict__ in,
    const float* __restrict__ w, int IC)
{
    __shared__ __align__(16) float ws[16][65];
    __shared__ __align__(16) float xs[16][64];

    const int tid = threadIdx.x;
    const int tx = tid & 15, ty = tid >> 4;
    const int p0 = blockIdx.x * 64;
    const int o0 = blockIdx.y * 64;

    float acc[4][4] = {};

    for (int c0 = 0; c0 < IC; c0 += 16) {
        __syncthreads();
#pragma unroll
        for (int i = 0; i < 4; i++) {
            int e = tid + i * 256;
            int oo = e >> 4, ck = e & 15;
            ws[ck][oo] = w[(o0 + oo) * IC + c0 + ck];
        }
#pragma unroll
        for (int i = 0; i < 4; i++) {
            int e = tid + i * 256;
            int ck = e >> 6, pp = e & 63;
            xs[ck][pp] = in[(c0 + ck) * NPOS + p0 + pp];
        }
        __syncthreads();
#pragma unroll
        for (int ck = 0; ck < 16; ck++) {
            float4 xv = *(const float4*)&xs[ck][tx * 4];
            float w0 = ws[ck][ty * 4 + 0];
            float w1 = ws[ck][ty * 4 + 1];
            float w2 = ws[ck][ty * 4 + 2];
            float w3 = ws[ck][ty * 4 + 3];
            acc[0][0] += w0 * xv.x; acc[0][1] += w0 * xv.y; acc[0][2] += w0 * xv.z; acc[0][3] += w0 * xv.w;
            acc[1][0] += w1 * xv.x; acc[1][1] += w1 * xv.y; acc[1][2] += w1 * xv.z; acc[1][3] += w1 * xv.w;
            acc[2][0] += w2 * xv.x; acc[2][1] += w2 * xv.y; acc[2][2] += w2 * xv.z; acc[2][3] += w2 * xv.w;
            acc[3][0] += w3 * xv.x; acc[3][1] += w3 * xv.y; acc[3][2] += w3 * xv.z; acc[3][3] += w3 * xv.w;
        }
    }
#pragma unroll
    for (int i = 0; i < 4; i++)
#pragma unroll
        for (int j = 0; j < 4; j++)
            out[(o0 + ty * 4 + i) * NPOS + p0 + tx * 4 + j] = acc[i][j];
}

// ---------------------------------------------------------------------------
// Depthwise 3x3 conv, padding=1
// ---------------------------------------------------------------------------
__global__ __launch_bounds__(256) void dw_conv_kernel(
    float* __restrict__ out, const float* __restrict__ in,
    const float* __restrict__ w)
{
    const int o = blockIdx.y;
    const int p = blockIdx.x * 256 + threadIdx.x;
    const int y = p >> 6, x = p & 63;
    const float* ip = in + o * NPOS;
    const float* wp = w + o * 9;
    float acc = 0.f;
#pragma unroll
    for (int dy = 0; dy < 3; dy++) {
        int yy = y + dy - 1;
        if (yy < 0 || yy > 63) continue;
#pragma unroll
        for (int dx = 0; dx < 3; dx++) {
            int xx = x + dx - 1;
            if (xx < 0 || xx > 63) continue;
            acc += wp[dy * 3 + dx] * ip[yy * 64 + xx];
        }
    }
    out[o * NPOS + p] = acc;
}

// ---------------------------------------------------------------------------
// L2-normalize q and k along head_dim(24); fold QK_SCALE into q.
// ---------------------------------------------------------------------------
__global__ __launch_bounds__(256) void norm_kernel(float* __restrict__ qkv)
{
    const int g = blockIdx.x * 256 + threadIdx.x;
    const int t = g >> 15;
    const int rem = g & 32767;
    const int h = rem >> 12;
    const int p = rem & 4095;
    float* base = qkv + (t * 192 + h * 24) * NPOS + p;
    float ss = 0.f;
#pragma unroll
    for (int d = 0; d < 24; d++) {
        float v = base[d * NPOS];
        ss += v * v;
    }
    float inv = 1.0f / fmaxf(sqrtf(ss), 1e-12f);
    if (t == 0) inv *= QK_SCALE;
#pragma unroll
    for (int d = 0; d < 24; d++)
        base[d * NPOS] *= inv;
}

// ---------------------------------------------------------------------------
// Flash-style attention, fp32 packed-f32x2, TWO query rows per lane.
// 128-thread CTAs (4 CTAs/SM: independent barriers, finer balance),
// double-buffered K/V tiles via cp.async (loads overlap compute).
// Scores bounded (unit-norm q,k; scale folded) => plain exp, additive split-K.
// Grid: (16 row-blocks of 256 rows, KSPLIT, 8 heads) = 512 CTAs.
// ---------------------------------------------------------------------------
__global__ __launch_bounds__(128, 4) void attn_kernel(
    float* __restrict__ pacc, float* __restrict__ pl,
    const float* __restrict__ qkv)
{
    __shared__ __align__(16) float ks[2][128 * 24];
    __shared__ __align__(16) float vs[2][128 * 24];

    const int tid   = threadIdx.x;
    const int head  = blockIdx.z;
    const int split = blockIdx.y;
    const int r0    = blockIdx.x * 256 + tid;
    const int r1    = r0 + 128;

    const float* qb = qkv + head * 24 * NPOS;
    const float* kb = qb + 192 * NPOS;
    const float* vb = kb + 192 * NPOS;

    const unsigned ks_s = (unsigned)__cvta_generic_to_shared(&ks[0][0]);
    const unsigned vs_s = (unsigned)__cvta_generic_to_shared(&vs[0][0]);

    const int kbase = split * (NPOS / KSPLIT);
    const int NT = (NPOS / KSPLIT) / 128;   // 8 tiles

    u64t q0[12], q1[12];
#pragma unroll
    for (int i = 0; i < 12; i++) {
        q0[i] = pack2(qb[(2 * i) * NPOS + r0], qb[(2 * i + 1) * NPOS + r0]);
        q1[i] = pack2(qb[(2 * i) * NPOS + r1], qb[(2 * i + 1) * NPOS + r1]);
    }

    u64t acc0[12], acc1[12];
#pragma unroll
    for (int i = 0; i < 12; i++) { acc0[i] = 0ull; acc1[i] = 0ull; }
    float l0 = 0.f, l1 = 0.f;

    // stage tile kt into buffer b (one commit group: K + V)
    auto stage = [&](int kt, int b) {
        const int j0 = kbase + kt * 128;
#pragma unroll
        for (int i = 0; i < 24; i++) {
            int e = i * 128 + tid;          // 3072 elems per array
            int d = e >> 7, j = e & 127;
            unsigned off = (unsigned)(b * 3072 + j * 24 + d) * 4u;
            const float* src = kb + d * NPOS + j0 + j;
            cp4(ks_s + off, src);
            cp4(vs_s + off, src + 192 * NPOS);  // vb = kb + 192*NPOS
        }
        asm volatile("cp.async.commit_group;" ::: "memory");
    };

    stage(0, 0);
    stage(1, 1);

    for (int kt = 0; kt < NT; kt++) {
        if (kt == NT - 1) asm volatile("cp.async.wait_group 0;" ::: "memory");
        else              asm volatile("cp.async.wait_group 1;" ::: "memory");
        __syncthreads();

        const float* ksp = ks[kt & 1];
        const float* vsp = vs[kt & 1];

#pragma unroll 4
        for (int j = 0; j < 128; j++) {
            const ulonglong2* kp = (const ulonglong2*)(ksp + j * 24);
            u64t sa0 = 0ull, sb0 = 0ull, sa1 = 0ull, sb1 = 0ull;
            {
                ulonglong2 t0 = kp[0], t1 = kp[1], t2 = kp[2];
                sa0 = ffma2(q0[0], t0.x, sa0);  sa1 = ffma2(q1[0], t0.x, sa1);
                sb0 = ffma2(q0[1], t0.y, sb0);  sb1 = ffma2(q1[1], t0.y, sb1);
                sa0 = ffma2(q0[2], t1.x, sa0);  sa1 = ffma2(q1[2], t1.x, sa1);
                sb0 = ffma2(q0[3], t1.y, sb0);  sb1 = ffma2(q1[3], t1.y, sb1);
                sa0 = ffma2(q0[4], t2.x, sa0);  sa1 = ffma2(q1[4], t2.x, sa1);
                sb0 = ffma2(q0[5], t2.y, sb0);  sb1 = ffma2(q1[5], t2.y, sb1);
            }
            {
                ulonglong2 t3 = kp[3], t4 = kp[4], t5 = kp[5];
                sa0 = ffma2(q0[6],  t3.x, sa0);  sa1 = ffma2(q1[6],  t3.x, sa1);
                sb0 = ffma2(q0[7],  t3.y, sb0);  sb1 = ffma2(q1[7],  t3.y, sb1);
                sa0 = ffma2(q0[8],  t4.x, sa0);  sa1 = ffma2(q1[8],  t4.x, sa1);
                sb0 = ffma2(q0[9],  t4.y, sb0);  sb1 = ffma2(q1[9],  t4.y, sb1);
                sa0 = ffma2(q0[10], t5.x, sa0);  sa1 = ffma2(q1[10], t5.x, sa1);
                sb0 = ffma2(q0[11], t5.y, sb0);  sb1 = ffma2(q1[11], t5.y, sb1);
            }

            float2 f0 = unpack2(fadd2(sa0, sb0));
            float2 f1 = unpack2(fadd2(sa1, sb1));
            float p0 = __expf(f0.x + f0.y);   // bounded scores — safe
            float p1 = __expf(f1.x + f1.y);
            l0 += p0;
            l1 += p1;
            u64t p20 = pack2(p0, p0);
            u64t p21 = pack2(p1, p1);

            const ulonglong2* vp = (const ulonglong2*)(vsp + j * 24);
            {
                ulonglong2 t0 = vp[0], t1 = vp[1], t2 = vp[2];
                acc0[0] = ffma2(p20, t0.x, acc0[0]);  acc1[0] = ffma2(p21, t0.x, acc1[0]);
                acc0[1] = ffma2(p20, t0.y, acc0[1]);  acc1[1] = ffma2(p21, t0.y, acc1[1]);
                acc0[2] = ffma2(p20, t1.x, acc0[2]);  acc1[2] = ffma2(p21, t1.x, acc1[2]);
                acc0[3] = ffma2(p20, t1.y, acc0[3]);  acc1[3] = ffma2(p21, t1.y, acc1[3]);
                acc0[4] = ffma2(p20, t2.x, acc0[4]);  acc1[4] = ffma2(p21, t2.x, acc1[4]);
                acc0[5] = ffma2(p20, t2.y, acc0[5]);  acc1[5] = ffma2(p21, t2.y, acc1[5]);
            }
            {
                ulonglong2 t3 = vp[3], t4 = vp[4], t5 = vp[5];
                acc0[6]  = ffma2(p20, t3.x, acc0[6]);   acc1[6]  = ffma2(p21, t3.x, acc1[6]);
                acc0[7]  = ffma2(p20, t3.y, acc0[7]);   acc1[7]  = ffma2(p21, t3.y, acc1[7]);
                acc0[8]  = ffma2(p20, t4.x, acc0[8]);   acc1[8]  = ffma2(p21, t4.x, acc1[8]);
                acc0[9]  = ffma2(p20, t4.y, acc0[9]);   acc1[9]  = ffma2(p21, t4.y, acc1[9]);
                acc0[10] = ffma2(p20, t5.x, acc0[10]);  acc1[10] = ffma2(p21, t5.x, acc1[10]);
                acc0[11] = ffma2(p20, t5.y, acc0[11]);  acc1[11] = ffma2(p21, t5.y, acc1[11]);
            }
        }

        __syncthreads();                 // done reading buf[kt&1]
        if (kt + 2 < NT) stage(kt + 2, kt & 1);
    }

    // Write partials (coalesced: lanes differ by row)
    float* pa0 = pacc + ((head * KSPLIT + split) * 24) * NPOS + r0;
    float* pa1 = pacc + ((head * KSPLIT + split) * 24) * NPOS + r1;
#pragma unroll
    for (int i = 0; i < 12; i++) {
        float2 f0 = unpack2(acc0[i]);
        float2 f1 = unpack2(acc1[i]);
        pa0[(2 * i) * NPOS]     = f0.x;
        pa0[(2 * i + 1) * NPOS] = f0.y;
        pa1[(2 * i) * NPOS]     = f1.x;
        pa1[(2 * i + 1) * NPOS] = f1.y;
    }
    pl[(head * KSPLIT + split) * NPOS + r0] = l0;
    pl[(head * KSPLIT + split) * NPOS + r1] = l1;
}

// ---------------------------------------------------------------------------
// Combine split-K partials (plain sums — no max bookkeeping needed).
// ---------------------------------------------------------------------------
__global__ __launch_bounds__(256) void combine_kernel(
    float* __restrict__ out, const float* __restrict__ pacc,
    const float* __restrict__ pl)
{
    const int g = blockIdx.x * 256 + threadIdx.x;   // 32768 = 8 heads * 4096 rows
    const int head = g >> 12, row = g & 4095;
    float l = 0.f;
#pragma unroll
    for (int s = 0; s < KSPLIT; s++)
        l += pl[(head * KSPLIT + s) * NPOS + row];
    const float inv = 1.0f / l;
#pragma unroll
    for (int d = 0; d < 24; d++) {
        float a = 0.f;
#pragma unroll
        for (int s = 0; s < KSPLIT; s++)
            a += pacc[((head * KSPLIT + s) * 24 + d) * NPOS + row];
        out[(head * 24 + d) * NPOS + row] = a * inv;
    }
}

// ---------------------------------------------------------------------------
extern "C" void kernel_launch(void* const* d_in, const int* in_sizes, int n_in,
                              void* d_out, int out_size)
{
    const float* x      = (const float*)d_in[0];
    const float* w_qkv  = (const float*)d_in[1];
    const float* w_dw   = (const float*)d_in[2];
    const float* w_proj = (const float*)d_in[3];
    float* out = (float*)d_out;

    float *b1, *b2, *at, *pa, *plv;
    cudaGetSymbolAddress((void**)&b1, g_buf1);
    cudaGetSymbolAddress((void**)&b2, g_buf2);
    cudaGetSymbolAddress((void**)&at, g_attn);
    cudaGetSymbolAddress((void**)&pa, g_pacc);
    cudaGetSymbolAddress((void**)&plv, g_pl);

    pw_conv_kernel<<<dim3(NPOS / 64, 576 / 64), 256>>>(b1, x, w_qkv, 192);
    dw_conv_kernel<<<dim3(NPOS / 256, 576), 256>>>(b2, b1, w_dw);
    norm_kernel<<<256, 256>>>(b2);
    attn_kernel<<<dim3(NPOS / 256, KSPLIT, 8), 128>>>(pa, plv, b2);
    combine_kernel<<<128, 256>>>(at, pa, plv);
    pw_conv_kernel<<<dim3(NPOS / 64, 192 / 64), 256>>>(out, at, w_proj, 192);
}

// round 7
// speedup vs baseline: 4.1114x; 2.7099x over previous
#include <cuda_runtime.h>
#include <cuda_fp16.h>
#include <math.h>
#include <stdint.h>

#define NPOS 4096
#define QK_SCALE 0.2041241452319315f  /* 24^-0.5 */

// Scratch (device globals — no allocation allowed)
__device__ float  g_buf1[576 * NPOS];        // qkv after 1x1 conv
__device__ float  g_buf2[576 * NPOS];        // qkv after dw conv
__device__ float  g_attn[192 * NPOS];        // attention output, [c][p]
__device__ __half g_q16[8 * NPOS * 24];      // normalized q (scale folded), [h][p][d]
__device__ __half g_k16[8 * NPOS * 24];      // normalized k, [h][p][d]
__device__ __half g_v16[8 * NPOS * 24];      // v, [h][p][d]

__device__ __forceinline__ uint32_t s2u(const void* p){
    uint32_t a;
    asm("{ .reg .u64 t; cvta.to.shared.u64 t, %1; cvt.u32.u64 %0, t; }" : "=r"(a) : "l"(p));
    return a;
}
#define LDSM_X4(r0,r1,r2,r3,a) \
    asm volatile("ldmatrix.sync.aligned.m8n8.x4.shared.b16 {%0,%1,%2,%3}, [%4];" \
        : "=r"(r0), "=r"(r1), "=r"(r2), "=r"(r3) : "r"(a))
#define LDSM_X4T(r0,r1,r2,r3,a) \
    asm volatile("ldmatrix.sync.aligned.m8n8.x4.trans.shared.b16 {%0,%1,%2,%3}, [%4];" \
        : "=r"(r0), "=r"(r1), "=r"(r2), "=r"(r3) : "r"(a))
#define LDSM_X2T(r0,r1,a) \
    asm volatile("ldmatrix.sync.aligned.m8n8.x2.trans.shared.b16 {%0,%1}, [%2];" \
        : "=r"(r0), "=r"(r1) : "r"(a))
#define MMA16816(c0,c1,c2,c3,a0,a1,a2,a3,b0,b1) \
    asm volatile("mma.sync.aligned.m16n8k16.row.col.f32.f16.f16.f32 " \
        "{%0,%1,%2,%3}, {%4,%5,%6,%7}, {%8,%9}, {%0,%1,%2,%3};" \
        : "+f"(c0), "+f"(c1), "+f"(c2), "+f"(c3) \
        : "r"(a0), "r"(a1), "r"(a2), "r"(a3), "r"(b0), "r"(b1))

// ---------------------------------------------------------------------------
// Pointwise (1x1) conv as GEMM: out[o][p] = sum_c w[o*IC+c] * in[c][p]
// ---------------------------------------------------------------------------
__global__ __launch_bounds__(256) void pw_conv_kernel(
    float* __restrict__ out, const float* __restrict__ in,
    const float* __restrict__ w, int IC)
{
    __shared__ __align__(16) float ws[16][65];
    __shared__ __align__(16) float xs[16][64];

    const int tid = threadIdx.x;
    const int tx = tid & 15, ty = tid >> 4;
    const int p0 = blockIdx.x * 64;
    const int o0 = blockIdx.y * 64;

    float acc[4][4] = {};

    for (int c0 = 0; c0 < IC; c0 += 16) {
        __syncthreads();
#pragma unroll
        for (int i = 0; i < 4; i++) {
            int e = tid + i * 256;
            int oo = e >> 4, ck = e & 15;
            ws[ck][oo] = w[(o0 + oo) * IC + c0 + ck];
        }
#pragma unroll
        for (int i = 0; i < 4; i++) {
            int e = tid + i * 256;
            int ck = e >> 6, pp = e & 63;
            xs[ck][pp] = in[(c0 + ck) * NPOS + p0 + pp];
        }
        __syncthreads();
#pragma unroll
        for (int ck = 0; ck < 16; ck++) {
            float4 xv = *(const float4*)&xs[ck][tx * 4];
            float w0 = ws[ck][ty * 4 + 0];
            float w1 = ws[ck][ty * 4 + 1];
            float w2 = ws[ck][ty * 4 + 2];
            float w3 = ws[ck][ty * 4 + 3];
            acc[0][0] += w0 * xv.x; acc[0][1] += w0 * xv.y; acc[0][2] += w0 * xv.z; acc[0][3] += w0 * xv.w;
            acc[1][0] += w1 * xv.x; acc[1][1] += w1 * xv.y; acc[1][2] += w1 * xv.z; acc[1][3] += w1 * xv.w;
            acc[2][0] += w2 * xv.x; acc[2][1] += w2 * xv.y; acc[2][2] += w2 * xv.z; acc[2][3] += w2 * xv.w;
            acc[3][0] += w3 * xv.x; acc[3][1] += w3 * xv.y; acc[3][2] += w3 * xv.z; acc[3][3] += w3 * xv.w;
        }
    }
#pragma unroll
    for (int i = 0; i < 4; i++)
#pragma unroll
        for (int j = 0; j < 4; j++)
            out[(o0 + ty * 4 + i) * NPOS + p0 + tx * 4 + j] = acc[i][j];
}

// ---------------------------------------------------------------------------
// Depthwise 3x3 conv, padding=1
// ---------------------------------------------------------------------------
__global__ __launch_bounds__(256) void dw_conv_kernel(
    float* __restrict__ out, const float* __restrict__ in,
    const float* __restrict__ w)
{
    const int o = blockIdx.y;
    const int p = blockIdx.x * 256 + threadIdx.x;
    const int y = p >> 6, x = p & 63;
    const float* ip = in + o * NPOS;
    const float* wp = w + o * 9;
    float acc = 0.f;
#pragma unroll
    for (int dy = 0; dy < 3; dy++) {
        int yy = y + dy - 1;
        if (yy < 0 || yy > 63) continue;
#pragma unroll
        for (int dx = 0; dx < 3; dx++) {
            int xx = x + dx - 1;
            if (xx < 0 || xx > 63) continue;
            acc += wp[dy * 3 + dx] * ip[yy * 64 + xx];
        }
    }
    out[o * NPOS + p] = acc;
}

// ---------------------------------------------------------------------------
// L2-normalize q,k (fold QK_SCALE into q) and emit fp16 [h][p][d] buffers;
// v converted to fp16 unchanged. t = 0:q, 1:k, 2:v. 98304 threads.
// ---------------------------------------------------------------------------
__global__ __launch_bounds__(256) void norm_cvt_kernel(
    const float* __restrict__ qkv, __half* __restrict__ q16,
    __half* __restrict__ k16, __half* __restrict__ v16)
{
    const int g = blockIdx.x * 256 + threadIdx.x;
    const int t = g >> 15;          // 0=q, 1=k, 2=v
    const int rem = g & 32767;
    const int h = rem >> 12;
    const int p = rem & 4095;
    const float* base = qkv + (t * 192 + h * 24) * NPOS + p;

    float v[24];
    float ss = 0.f;
#pragma unroll
    for (int d = 0; d < 24; d++) {
        v[d] = base[d * NPOS];
        ss += v[d] * v[d];
    }
    float inv;
    if (t == 0)      inv = QK_SCALE / fmaxf(sqrtf(ss), 1e-12f);
    else if (t == 1) inv = 1.0f / fmaxf(sqrtf(ss), 1e-12f);
    else             inv = 1.0f;

    __half* o = (t == 0 ? q16 : (t == 1 ? k16 : v16)) + (h * NPOS + p) * 24;
#pragma unroll
    for (int d = 0; d < 24; d++)
        o[d] = __float2half_rn(v[d] * inv);
}

// ---------------------------------------------------------------------------
// Flash attention via legacy mma.sync (m16n8k16 f16 -> f32 acc).
// CTA: 128 thr / 4 warps, 64 query rows (16 per warp). 32 key tiles of 128.
// QK: A = Q frags (d padded to 32), B = K via ldmatrix x4 (non-trans).
// Scores bounded ±0.205 -> plain __expf, no max tracking.
// P repacked in registers as A-frags (C->A layout identity); PV B = V via
// ldmatrix trans. O accumulates f32 in registers across all tiles.
// smem rows padded to 40 halfs (80B) -> conflict-free ldmatrix.
// Grid: (64 row tiles, 8 heads).
// ---------------------------------------------------------------------------
__global__ __launch_bounds__(128) void attn_kernel(
    float* __restrict__ out, const __half* __restrict__ q16,
    const __half* __restrict__ k16, const __half* __restrict__ v16)
{
    __shared__ __align__(16) __half sQ[64 * 40];
    __shared__ __align__(16) __half sK[128 * 40];
    __shared__ __align__(16) __half sV[128 * 40];

    const int tid  = threadIdx.x;
    const int lane = tid & 31, warp = tid >> 5;
    const int head = blockIdx.y;
    const int row0 = blockIdx.x * 64;

    uint32_t* sQu = (uint32_t*)sQ;
    uint32_t* sKu = (uint32_t*)sK;
    uint32_t* sVu = (uint32_t*)sV;

    // Stage Q tile (64 rows x 24 d) coalesced; zero-pad d24..31.
    {
        const uint32_t* qg = (const uint32_t*)(q16 + (head * NPOS + row0) * 24);
#pragma unroll
        for (int i = 0; i < 6; i++) {
            int e = i * 128 + tid;          // 768 uints
            int r = e / 12, u = e - 12 * r;
            sQu[r * 20 + u] = qg[e];
        }
#pragma unroll
        for (int i = 0; i < 2; i++) {
            int e = i * 128 + tid;          // 256 pad uints
            int r = e >> 2, u = e & 3;
            sQu[r * 20 + 12 + u] = 0u;
        }
        // zero-pad K d24..31 once (loads below only touch u 0..11)
#pragma unroll
        for (int i = 0; i < 4; i++) {
            int e = i * 128 + tid;          // 512 pad uints
            int r = e >> 2, u = e & 3;
            sKu[r * 20 + 12 + u] = 0u;
        }
    }
    __syncthreads();

    // Q A-fragments: two k16 steps (d 0-15, 16-31)
    uint32_t aq[2][4];
    {
        uint32_t qa = s2u(sQ) + (((warp * 16 + (lane & 15)) * 40 + (lane >> 4) * 8) << 1);
        LDSM_X4(aq[0][0], aq[0][1], aq[0][2], aq[0][3], qa);
        LDSM_X4(aq[1][0], aq[1][1], aq[1][2], aq[1][3], qa + 32);
    }

    float co[3][4] = {};
    float rl0 = 0.f, rl1 = 0.f;

    const uint32_t ka0 = s2u(sK) + ((((lane & 7) * 40) + (lane >> 3) * 8) << 1);
    const uint32_t va0 = s2u(sV) + ((((lane & 15) * 40) + (lane >> 4) * 8) << 1);
    const uint32_t va2 = s2u(sV) + ((((lane & 15) * 40) + 16) << 1);

    const uint32_t* kg_all = (const uint32_t*)(k16 + head * NPOS * 24);
    const uint32_t* vg_all = (const uint32_t*)(v16 + head * NPOS * 24);

    for (int t = 0; t < 32; t++) {
        __syncthreads();
        {
            const uint32_t* kg = kg_all + t * 128 * 12;
            const uint32_t* vg = vg_all + t * 128 * 12;
#pragma unroll
            for (int i = 0; i < 12; i++) {
                int e = i * 128 + tid;      // 1536 uints each
                int r = e / 12, u = e - 12 * r;
                int si = r * 20 + u;
                sKu[si] = kg[e];
                sVu[si] = vg[e];
            }
        }
        __syncthreads();

        uint32_t ap[16][2];
#pragma unroll
        for (int nt = 0; nt < 16; nt++) {
            uint32_t b0, b1, b2, b3;
            LDSM_X4(b0, b1, b2, b3, ka0 + nt * 640);
            float c0 = 0.f, c1 = 0.f, c2 = 0.f, c3 = 0.f;
            MMA16816(c0, c1, c2, c3, aq[0][0], aq[0][1], aq[0][2], aq[0][3], b0, b1);
            MMA16816(c0, c1, c2, c3, aq[1][0], aq[1][1], aq[1][2], aq[1][3], b2, b3);
            float p0 = __expf(c0), p1 = __expf(c1);
            float p2 = __expf(c2), p3 = __expf(c3);
            rl0 += p0 + p1;
            rl1 += p2 + p3;
            __half2 h01 = __floats2half2_rn(p0, p1);
            __half2 h23 = __floats2half2_rn(p2, p3);
            ap[nt][0] = *(uint32_t*)&h01;
            ap[nt][1] = *(uint32_t*)&h23;
        }

#pragma unroll
        for (int s = 0; s < 8; s++) {
            uint32_t b0, b1, b2, b3, b4, b5;
            LDSM_X4T(b0, b1, b2, b3, va0 + s * 1280);
            LDSM_X2T(b4, b5, va2 + s * 1280);
            uint32_t A0 = ap[2 * s][0], A1 = ap[2 * s][1];
            uint32_t A2 = ap[2 * s + 1][0], A3 = ap[2 * s + 1][1];
            MMA16816(co[0][0], co[0][1], co[0][2], co[0][3], A0, A1, A2, A3, b0, b1);
            MMA16816(co[1][0], co[1][1], co[1][2], co[1][3], A0, A1, A2, A3, b2, b3);
            MMA16816(co[2][0], co[2][1], co[2][2], co[2][3], A0, A1, A2, A3, b4, b5);
        }
    }

    // Row sums: reduce across the 4 lanes of each quad (same row group)
    rl0 += __shfl_xor_sync(0xFFFFFFFFu, rl0, 1);
    rl0 += __shfl_xor_sync(0xFFFFFFFFu, rl0, 2);
    rl1 += __shfl_xor_sync(0xFFFFFFFFu, rl1, 1);
    rl1 += __shfl_xor_sync(0xFFFFFFFFu, rl1, 2);
    const float inv0 = 1.0f / rl0;
    const float inv1 = 1.0f / rl1;

    const int gid = lane >> 2, tig = lane & 3;
    const int r0 = row0 + warp * 16 + gid;
#pragma unroll
    for (int nt = 0; nt < 3; nt++) {
        int d = nt * 8 + tig * 2;
        out[(head * 24 + d) * NPOS + r0]         = co[nt][0] * inv0;
        out[(head * 24 + d + 1) * NPOS + r0]     = co[nt][1] * inv0;
        out[(head * 24 + d) * NPOS + r0 + 8]     = co[nt][2] * inv1;
        out[(head * 24 + d + 1) * NPOS + r0 + 8] = co[nt][3] * inv1;
    }
}

// ---------------------------------------------------------------------------
extern "C" void kernel_launch(void* const* d_in, const int* in_sizes, int n_in,
                              void* d_out, int out_size)
{
    const float* x      = (const float*)d_in[0];
    const float* w_qkv  = (const float*)d_in[1];
    const float* w_dw   = (const float*)d_in[2];
    const float* w_proj = (const float*)d_in[3];
    float* out = (float*)d_out;

    float *b1, *b2, *at;
    __half *q16, *k16, *v16;
    cudaGetSymbolAddress((void**)&b1, g_buf1);
    cudaGetSymbolAddress((void**)&b2, g_buf2);
    cudaGetSymbolAddress((void**)&at, g_attn);
    cudaGetSymbolAddress((void**)&q16, g_q16);
    cudaGetSymbolAddress((void**)&k16, g_k16);
    cudaGetSymbolAddress((void**)&v16, g_v16);

    pw_conv_kernel<<<dim3(NPOS / 64, 576 / 64), 256>>>(b1, x, w_qkv, 192);
    dw_conv_kernel<<<dim3(NPOS / 256, 576), 256>>>(b2, b1, w_dw);
    norm_cvt_kernel<<<384, 256>>>(b2, q16, k16, v16);
    attn_kernel<<<dim3(NPOS / 64, 8), 128>>>(at, q16, k16, v16);
    pw_conv_kernel<<<dim3(NPOS / 64, 192 / 64), 256>>>(out, at, w_proj, 192);
}

// round 8
// speedup vs baseline: 4.1732x; 1.0150x over previous
#include <cuda_runtime.h>
#include <cuda_fp16.h>
#include <math.h>
#include <stdint.h>

#define NPOS 4096
#define QK_SCALE 0.2041241452319315f  /* 24^-0.5 */
#define KSPLIT 2

// Scratch (device globals — no allocation allowed)
__device__ float  g_buf1[576 * NPOS];             // qkv after 1x1 conv
__device__ float  g_attn[192 * NPOS];             // attention output, [c][p]
__device__ __half g_q16[8 * NPOS * 24];           // normalized q (scale folded), [h][p][d]
__device__ __half g_k16[8 * NPOS * 24];           // normalized k, [h][p][d]
__device__ __half g_v16[8 * NPOS * 24];           // v, [h][p][d]
__device__ float  g_pacc[8 * KSPLIT * 24 * NPOS]; // split-K partial acc
__device__ float  g_pl[8 * KSPLIT * NPOS];        // split-K partial l

__device__ __forceinline__ uint32_t s2u(const void* p){
    uint32_t a;
    asm("{ .reg .u64 t; cvta.to.shared.u64 t, %1; cvt.u32.u64 %0, t; }" : "=r"(a) : "l"(p));
    return a;
}
#define LDSM_X4(r0,r1,r2,r3,a) \
    asm volatile("ldmatrix.sync.aligned.m8n8.x4.shared.b16 {%0,%1,%2,%3}, [%4];" \
        : "=r"(r0), "=r"(r1), "=r"(r2), "=r"(r3) : "r"(a))
#define LDSM_X4T(r0,r1,r2,r3,a) \
    asm volatile("ldmatrix.sync.aligned.m8n8.x4.trans.shared.b16 {%0,%1,%2,%3}, [%4];" \
        : "=r"(r0), "=r"(r1), "=r"(r2), "=r"(r3) : "r"(a))
#define LDSM_X2T(r0,r1,a) \
    asm volatile("ldmatrix.sync.aligned.m8n8.x2.trans.shared.b16 {%0,%1}, [%2];" \
        : "=r"(r0), "=r"(r1) : "r"(a))
#define MMA16816(c0,c1,c2,c3,a0,a1,a2,a3,b0,b1) \
    asm volatile("mma.sync.aligned.m16n8k16.row.col.f32.f16.f16.f32 " \
        "{%0,%1,%2,%3}, {%4,%5,%6,%7}, {%8,%9}, {%0,%1,%2,%3};" \
        : "+f"(c0), "+f"(c1), "+f"(c2), "+f"(c3) \
        : "r"(a0), "r"(a1), "r"(a2), "r"(a3), "r"(b0), "r"(b1))
#define CP16(dst, src) \
    asm volatile("cp.async.cg.shared.global [%0], [%1], 16;" :: "r"(dst), "l"(src))

// ---------------------------------------------------------------------------
// Pointwise (1x1) conv as GEMM: out[o][p] = sum_c w[o*IC+c] * in[c][p]
// ---------------------------------------------------------------------------
__global__ __launch_bounds__(256) void pw_conv_kernel(
    float* __restrict__ out, const float* __restrict__ in,
    const float* __restrict__ w, int IC)
{
    __shared__ __align__(16) float ws[16][65];
    __shared__ __align__(16) float xs[16][64];

    const int tid = threadIdx.x;
    const int tx = tid & 15, ty = tid >> 4;
    const int p0 = blockIdx.x * 64;
    const int o0 = blockIdx.y * 64;

    float acc[4][4] = {};

    for (int c0 = 0; c0 < IC; c0 += 16) {
        __syncthreads();
#pragma unroll
        for (int i = 0; i < 4; i++) {
            int e = tid + i * 256;
            int oo = e >> 4, ck = e & 15;
            ws[ck][oo] = w[(o0 + oo) * IC + c0 + ck];
        }
#pragma unroll
        for (int i = 0; i < 4; i++) {
            int e = tid + i * 256;
            int ck = e >> 6, pp = e & 63;
            xs[ck][pp] = in[(c0 + ck) * NPOS + p0 + pp];
        }
        __syncthreads();
#pragma unroll
        for (int ck = 0; ck < 16; ck++) {
            float4 xv = *(const float4*)&xs[ck][tx * 4];
            float w0 = ws[ck][ty * 4 + 0];
            float w1 = ws[ck][ty * 4 + 1];
            float w2 = ws[ck][ty * 4 + 2];
            float w3 = ws[ck][ty * 4 + 3];
            acc[0][0] += w0 * xv.x; acc[0][1] += w0 * xv.y; acc[0][2] += w0 * xv.z; acc[0][3] += w0 * xv.w;
            acc[1][0] += w1 * xv.x; acc[1][1] += w1 * xv.y; acc[1][2] += w1 * xv.z; acc[1][3] += w1 * xv.w;
            acc[2][0] += w2 * xv.x; acc[2][1] += w2 * xv.y; acc[2][2] += w2 * xv.z; acc[2][3] += w2 * xv.w;
            acc[3][0] += w3 * xv.x; acc[3][1] += w3 * xv.y; acc[3][2] += w3 * xv.z; acc[3][3] += w3 * xv.w;
        }
    }
#pragma unroll
    for (int i = 0; i < 4; i++)
#pragma unroll
        for (int j = 0; j < 4; j++)
            out[(o0 + ty * 4 + i) * NPOS + p0 + tx * 4 + j] = acc[i][j];
}

// ---------------------------------------------------------------------------
// Fused: depthwise 3x3 (padding=1) + L2-normalize along head_dim(24) +
// fp16 convert. Thread = (tensor t, head h, position p). 98304 threads.
// q gets QK_SCALE folded in; k normalized; v passthrough.
// ---------------------------------------------------------------------------
__global__ __launch_bounds__(256) void dwnorm_kernel(
    const float* __restrict__ in, const float* __restrict__ wdw,
    __half* __restrict__ q16, __half* __restrict__ k16, __half* __restrict__ v16)
{
    const int g = blockIdx.x * 256 + threadIdx.x;
    const int t = g >> 15;          // 0=q, 1=k, 2=v
    const int rem = g & 32767;
    const int h = rem >> 12;
    const int p = rem & 4095;
    const int y = p >> 6, x = p & 63;

    const float* ipb = in + (t * 192 + h * 24) * NPOS;
    const float* wpb = wdw + (t * 192 + h * 24) * 9;

    const bool ym = (y > 0), yp = (y < 63);
    const bool xm = (x > 0), xp = (x < 63);

    float v[24];
    float ss = 0.f;
#pragma unroll
    for (int d = 0; d < 24; d++) {
        const float* ip = ipb + d * NPOS + p;
        const float* wp = wpb + d * 9;
        float a = wp[4] * ip[0];
        if (ym) {
            a += wp[1] * ip[-64];
            if (xm) a += wp[0] * ip[-65];
            if (xp) a += wp[2] * ip[-63];
        }
        if (xm) a += wp[3] * ip[-1];
        if (xp) a += wp[5] * ip[1];
        if (yp) {
            a += wp[7] * ip[64];
            if (xm) a += wp[6] * ip[63];
            if (xp) a += wp[8] * ip[65];
        }
        v[d] = a;
        ss += a * a;
    }
    float inv;
    if (t == 0)      inv = QK_SCALE / fmaxf(sqrtf(ss), 1e-12f);
    else if (t == 1) inv = 1.0f / fmaxf(sqrtf(ss), 1e-12f);
    else             inv = 1.0f;

    __half* o = (t == 0 ? q16 : (t == 1 ? k16 : v16)) + (h * NPOS + p) * 24;
#pragma unroll
    for (int d = 0; d < 24; d++)
        o[d] = __float2half_rn(v[d] * inv);
}

// ---------------------------------------------------------------------------
// Flash attention via mma.sync m16n8k16, split-K = 2.
// CTA: 128 thr / 4 warps, 64 query rows; 16 key tiles of 128 per split.
// K/V staged with cp.async.cg 16B (3 float4/thread/array per tile).
// Scores bounded ±0.205 -> plain __expf, no max tracking; partials additive.
// Grid: (64 row tiles, 8 heads, KSPLIT).
// ---------------------------------------------------------------------------
__global__ __launch_bounds__(128) void attn_kernel(
    float* __restrict__ pacc, float* __restrict__ pl,
    const __half* __restrict__ q16, const __half* __restrict__ k16,
    const __half* __restrict__ v16)
{
    __shared__ __align__(16) __half sQ[64 * 40];
    __shared__ __align__(16) __half sK[128 * 40];
    __shared__ __align__(16) __half sV[128 * 40];

    const int tid   = threadIdx.x;
    const int lane  = tid & 31, warp = tid >> 5;
    const int head  = blockIdx.y;
    const int split = blockIdx.z;
    const int row0  = blockIdx.x * 64;

    uint32_t* sQu = (uint32_t*)sQ;
    uint32_t* sKu = (uint32_t*)sK;

    // Stage Q tile (64 rows x 24 d) coalesced; zero-pad Q and K d24..31.
    {
        const uint32_t* qg = (const uint32_t*)(q16 + (head * NPOS + row0) * 24);
#pragma unroll
        for (int i = 0; i < 6; i++) {
            int e = i * 128 + tid;          // 768 uints
            int r = e / 12, u = e - 12 * r;
            sQu[r * 20 + u] = qg[e];
        }
#pragma unroll
        for (int i = 0; i < 2; i++) {
            int e = i * 128 + tid;          // 256 pad uints
            int r = e >> 2, u = e & 3;
            sQu[r * 20 + 12 + u] = 0u;
        }
#pragma unroll
        for (int i = 0; i < 4; i++) {
            int e = i * 128 + tid;          // 512 pad uints (K rows)
            int r = e >> 2, u = e & 3;
            sKu[r * 20 + 12 + u] = 0u;
        }
    }
    __syncthreads();

    // Q A-fragments: two k16 steps (d 0-15, 16-31)
    uint32_t aq[2][4];
    {
        uint32_t qa = s2u(sQ) + (((warp * 16 + (lane & 15)) * 40 + (lane >> 4) * 8) << 1);
        LDSM_X4(aq[0][0], aq[0][1], aq[0][2], aq[0][3], qa);
        LDSM_X4(aq[1][0], aq[1][1], aq[1][2], aq[1][3], qa + 32);
    }

    float co[3][4] = {};
    float rl0 = 0.f, rl1 = 0.f;

    const uint32_t ka0 = s2u(sK) + ((((lane & 7) * 40) + (lane >> 3) * 8) << 1);
    const uint32_t va0 = s2u(sV) + ((((lane & 15) * 40) + (lane >> 4) * 8) << 1);
    const uint32_t va2 = s2u(sV) + ((((lane & 15) * 40) + 16) << 1);
    const uint32_t sK_s = s2u(sK), sV_s = s2u(sV);

    const uint4* kg4 = (const uint4*)(k16 + head * NPOS * 24);
    const uint4* vg4 = (const uint4*)(v16 + head * NPOS * 24);
    const int tbase = split * (32 / KSPLIT);

    for (int t = 0; t < 32 / KSPLIT; t++) {
        // stage tile via cp.async: 384 float4 per array, rows of 48B (3x16B)
        {
            const uint4* kg = kg4 + (tbase + t) * 384;
            const uint4* vg = vg4 + (tbase + t) * 384;
#pragma unroll
            for (int i = 0; i < 3; i++) {
                int e = i * 128 + tid;      // 0..383
                int r = e / 3, m = e - 3 * r;
                uint32_t off = (uint32_t)(r * 80 + m * 16);
                CP16(sK_s + off, kg + e);
                CP16(sV_s + off, vg + e);
            }
            asm volatile("cp.async.commit_group;" ::: "memory");
            asm volatile("cp.async.wait_group 0;" ::: "memory");
        }
        __syncthreads();

        uint32_t ap[16][2];
#pragma unroll
        for (int nt = 0; nt < 16; nt++) {
            uint32_t b0, b1, b2, b3;
            LDSM_X4(b0, b1, b2, b3, ka0 + nt * 640);
            float c0 = 0.f, c1 = 0.f, c2 = 0.f, c3 = 0.f;
            MMA16816(c0, c1, c2, c3, aq[0][0], aq[0][1], aq[0][2], aq[0][3], b0, b1);
            MMA16816(c0, c1, c2, c3, aq[1][0], aq[1][1], aq[1][2], aq[1][3], b2, b3);
            float p0 = __expf(c0), p1 = __expf(c1);
            float p2 = __expf(c2), p3 = __expf(c3);
            rl0 += p0 + p1;
            rl1 += p2 + p3;
            __half2 h01 = __floats2half2_rn(p0, p1);
            __half2 h23 = __floats2half2_rn(p2, p3);
            ap[nt][0] = *(uint32_t*)&h01;
            ap[nt][1] = *(uint32_t*)&h23;
        }

#pragma unroll
        for (int s = 0; s < 8; s++) {
            uint32_t b0, b1, b2, b3, b4, b5;
            LDSM_X4T(b0, b1, b2, b3, va0 + s * 1280);
            LDSM_X2T(b4, b5, va2 + s * 1280);
            uint32_t A0 = ap[2 * s][0], A1 = ap[2 * s][1];
            uint32_t A2 = ap[2 * s + 1][0], A3 = ap[2 * s + 1][1];
            MMA16816(co[0][0], co[0][1], co[0][2], co[0][3], A0, A1, A2, A3, b0, b1);
            MMA16816(co[1][0], co[1][1], co[1][2], co[1][3], A0, A1, A2, A3, b2, b3);
            MMA16816(co[2][0], co[2][1], co[2][2], co[2][3], A0, A1, A2, A3, b4, b5);
        }
        __syncthreads();
    }

    // Row sums: reduce across the 4 lanes of each quad
    rl0 += __shfl_xor_sync(0xFFFFFFFFu, rl0, 1);
    rl0 += __shfl_xor_sync(0xFFFFFFFFu, rl0, 2);
    rl1 += __shfl_xor_sync(0xFFFFFFFFu, rl1, 1);
    rl1 += __shfl_xor_sync(0xFFFFFFFFu, rl1, 2);

    const int gid = lane >> 2, tig = lane & 3;
    const int r0 = row0 + warp * 16 + gid;
    const int sb = head * KSPLIT + split;

    float* pa = pacc + sb * 24 * NPOS;
#pragma unroll
    for (int nt = 0; nt < 3; nt++) {
        int d = nt * 8 + tig * 2;
        pa[(d) * NPOS + r0]         = co[nt][0];
        pa[(d + 1) * NPOS + r0]     = co[nt][1];
        pa[(d) * NPOS + r0 + 8]     = co[nt][2];
        pa[(d + 1) * NPOS + r0 + 8] = co[nt][3];
    }
    if (tig == 0) {
        pl[sb * NPOS + r0]     = rl0;
        pl[sb * NPOS + r0 + 8] = rl1;
    }
}

// ---------------------------------------------------------------------------
// Combine split-K partials (plain sums — bounded scores, no max bookkeeping).
// ---------------------------------------------------------------------------
__global__ __launch_bounds__(256) void combine_kernel(
    float* __restrict__ out, const float* __restrict__ pacc,
    const float* __restrict__ pl)
{
    const int g = blockIdx.x * 256 + threadIdx.x;   // 32768 = 8 heads * 4096 rows
    const int head = g >> 12, row = g & 4095;
    float l = 0.f;
#pragma unroll
    for (int s = 0; s < KSPLIT; s++)
        l += pl[(head * KSPLIT + s) * NPOS + row];
    const float inv = 1.0f / l;
#pragma unroll
    for (int d = 0; d < 24; d++) {
        float a = 0.f;
#pragma unroll
        for (int s = 0; s < KSPLIT; s++)
            a += pacc[((head * KSPLIT + s) * 24 + d) * NPOS + row];
        out[(head * 24 + d) * NPOS + row] = a * inv;
    }
}

// ---------------------------------------------------------------------------
extern "C" void kernel_launch(void* const* d_in, const int* in_sizes, int n_in,
                              void* d_out, int out_size)
{
    const float* x      = (const float*)d_in[0];
    const float* w_qkv  = (const float*)d_in[1];
    const float* w_dw   = (const float*)d_in[2];
    const float* w_proj = (const float*)d_in[3];
    float* out = (float*)d_out;

    float *b1, *at, *pa, *plv;
    __half *q16, *k16, *v16;
    cudaGetSymbolAddress((void**)&b1, g_buf1);
    cudaGetSymbolAddress((void**)&at, g_attn);
    cudaGetSymbolAddress((void**)&pa, g_pacc);
    cudaGetSymbolAddress((void**)&plv, g_pl);
    cudaGetSymbolAddress((void**)&q16, g_q16);
    cudaGetSymbolAddress((void**)&k16, g_k16);
    cudaGetSymbolAddress((void**)&v16, g_v16);

    pw_conv_kernel<<<dim3(NPOS / 64, 576 / 64), 256>>>(b1, x, w_qkv, 192);
    dwnorm_kernel<<<384, 256>>>(b1, w_dw, q16, k16, v16);
    attn_kernel<<<dim3(NPOS / 64, 8, KSPLIT), 128>>>(pa, plv, q16, k16, v16);
    combine_kernel<<<128, 256>>>(at, pa, plv);
    pw_conv_kernel<<<dim3(NPOS / 64, 192 / 64), 256>>>(out, at, w_proj, 192);
}

// round 9
// speedup vs baseline: 5.2210x; 1.2511x over previous
#include <cuda_runtime.h>
#include <cuda_fp16.h>
#include <math.h>
#include <stdint.h>

#define NPOS 4096
#define QK_SCALE 0.2041241452319315f  /* 24^-0.5 */
#define KSPLIT 2

// Scratch (device globals — no allocation allowed)
__device__ float  g_attn[192 * NPOS];             // attention output, [c][p]
__device__ __half g_qkv16[576 * NPOS];            // qkv after 1x1 conv, fp16 [o][p]
__device__ __half g_q16[8 * NPOS * 24];           // normalized q (scale folded), [h][p][d]
__device__ __half g_k16[8 * NPOS * 24];           // normalized k, [h][p][d]
__device__ __half g_v16[8 * NPOS * 24];           // v, [h][p][d]
__device__ float  g_pacc[8 * KSPLIT * 24 * NPOS]; // split-K partial acc
__device__ float  g_pl[8 * KSPLIT * NPOS];        // split-K partial l

__device__ __forceinline__ uint32_t s2u(const void* p){
    uint32_t a;
    asm("{ .reg .u64 t; cvta.to.shared.u64 t, %1; cvt.u32.u64 %0, t; }" : "=r"(a) : "l"(p));
    return a;
}
#define LDSM_X4(r0,r1,r2,r3,a) \
    asm volatile("ldmatrix.sync.aligned.m8n8.x4.shared.b16 {%0,%1,%2,%3}, [%4];" \
        : "=r"(r0), "=r"(r1), "=r"(r2), "=r"(r3) : "r"(a))
#define LDSM_X4T(r0,r1,r2,r3,a) \
    asm volatile("ldmatrix.sync.aligned.m8n8.x4.trans.shared.b16 {%0,%1,%2,%3}, [%4];" \
        : "=r"(r0), "=r"(r1), "=r"(r2), "=r"(r3) : "r"(a))
#define LDSM_X2T(r0,r1,a) \
    asm volatile("ldmatrix.sync.aligned.m8n8.x2.trans.shared.b16 {%0,%1}, [%2];" \
        : "=r"(r0), "=r"(r1) : "r"(a))
#define MMA16816(c0,c1,c2,c3,a0,a1,a2,a3,b0,b1) \
    asm volatile("mma.sync.aligned.m16n8k16.row.col.f32.f16.f16.f32 " \
        "{%0,%1,%2,%3}, {%4,%5,%6,%7}, {%8,%9}, {%0,%1,%2,%3};" \
        : "+f"(c0), "+f"(c1), "+f"(c2), "+f"(c3) \
        : "r"(a0), "r"(a1), "r"(a2), "r"(a3), "r"(b0), "r"(b1))
#define CP16(dst, src) \
    asm volatile("cp.async.cg.shared.global [%0], [%1], 16;" :: "r"(dst), "l"(src))

// ---------------------------------------------------------------------------
// qkv 1x1 conv via fp16 mma: out16[o][p] = sum_c w[o][c] * x[c][p]
// CTA: 128 thr / 4 warps, tile O=64 x P=64. A (weights) staged once;
// B (x) staged per k16 step with register prefetch overlapping MMA.
// Grid: (4096/64, 576/64) = (64, 9).
// ---------------------------------------------------------------------------
__global__ __launch_bounds__(128) void pw1_mma_kernel(
    __half* __restrict__ out16, const float* __restrict__ x,
    const float* __restrict__ w)
{
    __shared__ __align__(16) __half sA[64 * 200];  // [o][k], pad 192->200
    __shared__ __align__(16) __half sB[16 * 72];   // [k16][p64], pad 64->72

    const int tid  = threadIdx.x;
    const int lane = tid & 31, warp = tid >> 5;
    const int p0 = blockIdx.x * 64;
    const int o0 = blockIdx.y * 64;

    // Stage A: 64 rows x 192 k, f32 -> f16 (3072 float4, 24/thread)
    {
        const float4* wg = (const float4*)(w + o0 * 192);
#pragma unroll
        for (int i = 0; i < 24; i++) {
            int e = i * 128 + tid;
            int r = e / 48, m = e - 48 * r;
            float4 f = wg[e];
            *(__half2*)(sA + r * 200 + m * 4)     = __floats2half2_rn(f.x, f.y);
            *(__half2*)(sA + r * 200 + m * 4 + 2) = __floats2half2_rn(f.z, f.w);
        }
    }

    float acc[8][4] = {};

    // register prefetch of B block for kstep 0
    float4 pf[2];
#pragma unroll
    for (int i = 0; i < 2; i++) {
        int e = i * 128 + tid;                 // 256 float4 = 16x64 floats
        int kk = e >> 4, m = e & 15;
        pf[i] = *(const float4*)(x + kk * NPOS + p0 + m * 4);
    }

    const uint32_t sA_s = s2u(sA), sB_s = s2u(sB);

    for (int ks = 0; ks < 12; ks++) {
        __syncthreads();                       // protect sB reuse
#pragma unroll
        for (int i = 0; i < 2; i++) {
            int e = i * 128 + tid;
            int kk = e >> 4, m = e & 15;
            *(__half2*)(sB + kk * 72 + m * 4)     = __floats2half2_rn(pf[i].x, pf[i].y);
            *(__half2*)(sB + kk * 72 + m * 4 + 2) = __floats2half2_rn(pf[i].z, pf[i].w);
        }
        __syncthreads();

        if (ks + 1 < 12) {
#pragma unroll
            for (int i = 0; i < 2; i++) {
                int e = i * 128 + tid;
                int kk = e >> 4, m = e & 15;
                pf[i] = *(const float4*)(x + ((ks + 1) * 16 + kk) * NPOS + p0 + m * 4);
            }
        }

        uint32_t a0, a1, a2, a3;
        LDSM_X4(a0, a1, a2, a3,
                sA_s + (((warp * 16 + (lane & 15)) * 200 + ks * 16 + (lane >> 4) * 8) << 1));
#pragma unroll
        for (int c = 0; c < 4; c++) {
            uint32_t b0, b1, b2, b3;
            LDSM_X4T(b0, b1, b2, b3,
                     sB_s + (((lane & 15) * 72 + c * 16 + (lane >> 4) * 8) << 1));
            MMA16816(acc[2*c][0], acc[2*c][1], acc[2*c][2], acc[2*c][3],
                     a0, a1, a2, a3, b0, b1);
            MMA16816(acc[2*c+1][0], acc[2*c+1][1], acc[2*c+1][2], acc[2*c+1][3],
                     a0, a1, a2, a3, b2, b3);
        }
    }

    const int gid = lane >> 2, tig = lane & 3;
    const int o = o0 + warp * 16 + gid;
#pragma unroll
    for (int c8 = 0; c8 < 8; c8++) {
        int p = p0 + c8 * 8 + tig * 2;
        *(__half2*)&out16[o * NPOS + p]       = __floats2half2_rn(acc[c8][0], acc[c8][1]);
        *(__half2*)&out16[(o + 8) * NPOS + p] = __floats2half2_rn(acc[c8][2], acc[c8][3]);
    }
}

// ---------------------------------------------------------------------------
// Fused: depthwise 3x3 (padding=1, fp16 input) + L2-normalize (24) + fp16 out.
// ---------------------------------------------------------------------------
__global__ __launch_bounds__(256) void dwnorm_kernel(
    const __half* __restrict__ in, const float* __restrict__ wdw,
    __half* __restrict__ q16, __half* __restrict__ k16, __half* __restrict__ v16)
{
    const int g = blockIdx.x * 256 + threadIdx.x;
    const int t = g >> 15;          // 0=q, 1=k, 2=v
    const int rem = g & 32767;
    const int h = rem >> 12;
    const int p = rem & 4095;
    const int y = p >> 6, x = p & 63;

    const __half* ipb = in + (t * 192 + h * 24) * NPOS;
    const float* wpb = wdw + (t * 192 + h * 24) * 9;

    const bool ym = (y > 0), yp = (y < 63);
    const bool xm = (x > 0), xp = (x < 63);

    float v[24];
    float ss = 0.f;
#pragma unroll
    for (int d = 0; d < 24; d++) {
        const __half* ip = ipb + d * NPOS + p;
        const float* wp = wpb + d * 9;
        float a = wp[4] * __half2float(ip[0]);
        if (ym) {
            a += wp[1] * __half2float(ip[-64]);
            if (xm) a += wp[0] * __half2float(ip[-65]);
            if (xp) a += wp[2] * __half2float(ip[-63]);
        }
        if (xm) a += wp[3] * __half2float(ip[-1]);
        if (xp) a += wp[5] * __half2float(ip[1]);
        if (yp) {
            a += wp[7] * __half2float(ip[64]);
            if (xm) a += wp[6] * __half2float(ip[63]);
            if (xp) a += wp[8] * __half2float(ip[65]);
        }
        v[d] = a;
        ss += a * a;
    }
    float inv;
    if (t == 0)      inv = QK_SCALE / fmaxf(sqrtf(ss), 1e-12f);
    else if (t == 1) inv = 1.0f / fmaxf(sqrtf(ss), 1e-12f);
    else             inv = 1.0f;

    __half* o = (t == 0 ? q16 : (t == 1 ? k16 : v16)) + (h * NPOS + p) * 24;
#pragma unroll
    for (int d = 0; d < 24; d++)
        o[d] = __float2half_rn(v[d] * inv);
}

// ---------------------------------------------------------------------------
// Flash attention via mma.sync m16n8k16, split-K=2, double-buffered cp.async.
// CTA: 128 thr / 4 warps, 64 query rows; 16 key tiles of 128 per split.
// Scores bounded ±0.205 -> plain __expf, no max tracking; partials additive.
// Grid: (64 row tiles, 8 heads, KSPLIT).
// ---------------------------------------------------------------------------
__global__ __launch_bounds__(128) void attn_kernel(
    float* __restrict__ pacc, float* __restrict__ pl,
    const __half* __restrict__ q16, const __half* __restrict__ k16,
    const __half* __restrict__ v16)
{
    __shared__ __align__(16) __half sQ[64 * 40];        // 5 KB
    __shared__ __align__(16) __half sK[2][128 * 40];    // 20 KB
    __shared__ __align__(16) __half sV[2][128 * 40];    // 20 KB

    const int tid   = threadIdx.x;
    const int lane  = tid & 31, warp = tid >> 5;
    const int head  = blockIdx.y;
    const int split = blockIdx.z;
    const int row0  = blockIdx.x * 64;

    uint32_t* sQu = (uint32_t*)sQ;
    uint32_t* sKu = (uint32_t*)sK;

    // Stage Q tile (64 rows x 24 d) coalesced; zero-pad Q d24..31 and
    // K d24..31 in BOTH buffers (cp.async only writes bytes 0..47 per row).
    {
        const uint32_t* qg = (const uint32_t*)(q16 + (head * NPOS + row0) * 24);
#pragma unroll
        for (int i = 0; i < 6; i++) {
            int e = i * 128 + tid;          // 768 uints
            int r = e / 12, u = e - 12 * r;
            sQu[r * 20 + u] = qg[e];
        }
#pragma unroll
        for (int i = 0; i < 2; i++) {
            int e = i * 128 + tid;          // 256 pad uints
            int r = e >> 2, u = e & 3;
            sQu[r * 20 + 12 + u] = 0u;
        }
#pragma unroll
        for (int i = 0; i < 8; i++) {       // 1024 pad uints (256 rows over 2 bufs)
            int e = i * 128 + tid;
            int r = e >> 2, u = e & 3;
            sKu[r * 20 + 12 + u] = 0u;
        }
    }
    __syncthreads();

    // Q A-fragments: two k16 steps (d 0-15, 16-31)
    uint32_t aq[2][4];
    {
        uint32_t qa = s2u(sQ) + (((warp * 16 + (lane & 15)) * 40 + (lane >> 4) * 8) << 1);
        LDSM_X4(aq[0][0], aq[0][1], aq[0][2], aq[0][3], qa);
        LDSM_X4(aq[1][0], aq[1][1], aq[1][2], aq[1][3], qa + 32);
    }

    float co[3][4] = {};
    float rl0 = 0.f, rl1 = 0.f;

    const uint32_t sK_s = s2u(sK), sV_s = s2u(sV);
    const uint32_t ka0 = sK_s + ((((lane & 7) * 40) + (lane >> 3) * 8) << 1);
    const uint32_t va0 = sV_s + ((((lane & 15) * 40) + (lane >> 4) * 8) << 1);
    const uint32_t va2 = sV_s + ((((lane & 15) * 40) + 16) << 1);

    const uint4* kg4 = (const uint4*)(k16 + head * NPOS * 24);
    const uint4* vg4 = (const uint4*)(v16 + head * NPOS * 24);
    const int tbase = split * (32 / KSPLIT);
    const int NT = 32 / KSPLIT;

    // stage tile tt into buffer b: 384 float4 per array, rows of 48B (3x16B)
    auto stage = [&](int tt, int b) {
        const uint4* kg = kg4 + (tbase + tt) * 384;
        const uint4* vg = vg4 + (tbase + tt) * 384;
        const uint32_t bo = (uint32_t)b * 10240u;
#pragma unroll
        for (int i = 0; i < 3; i++) {
            int e = i * 128 + tid;
            int r = e / 3, m = e - 3 * r;
            uint32_t off = bo + (uint32_t)(r * 80 + m * 16);
            CP16(sK_s + off, kg + e);
            CP16(sV_s + off, vg + e);
        }
        asm volatile("cp.async.commit_group;" ::: "memory");
    };

    stage(0, 0);

    for (int t = 0; t < NT; t++) {
        if (t + 1 < NT) {
            stage(t + 1, (t + 1) & 1);
            asm volatile("cp.async.wait_group 1;" ::: "memory");
        } else {
            asm volatile("cp.async.wait_group 0;" ::: "memory");
        }
        __syncthreads();

        const uint32_t bo = (uint32_t)(t & 1) * 10240u;

        uint32_t ap[16][2];
#pragma unroll
        for (int nt = 0; nt < 16; nt++) {
            uint32_t b0, b1, b2, b3;
            LDSM_X4(b0, b1, b2, b3, ka0 + bo + nt * 640);
            float c0 = 0.f, c1 = 0.f, c2 = 0.f, c3 = 0.f;
            MMA16816(c0, c1, c2, c3, aq[0][0], aq[0][1], aq[0][2], aq[0][3], b0, b1);
            MMA16816(c0, c1, c2, c3, aq[1][0], aq[1][1], aq[1][2], aq[1][3], b2, b3);
            float p0 = __expf(c0), p1 = __expf(c1);
            float p2 = __expf(c2), p3 = __expf(c3);
            rl0 += p0 + p1;
            rl1 += p2 + p3;
            __half2 h01 = __floats2half2_rn(p0, p1);
            __half2 h23 = __floats2half2_rn(p2, p3);
            ap[nt][0] = *(uint32_t*)&h01;
            ap[nt][1] = *(uint32_t*)&h23;
        }

#pragma unroll
        for (int s = 0; s < 8; s++) {
            uint32_t b0, b1, b2, b3, b4, b5;
            LDSM_X4T(b0, b1, b2, b3, va0 + bo + s * 1280);
            LDSM_X2T(b4, b5, va2 + bo + s * 1280);
            uint32_t A0 = ap[2 * s][0], A1 = ap[2 * s][1];
            uint32_t A2 = ap[2 * s + 1][0], A3 = ap[2 * s + 1][1];
            MMA16816(co[0][0], co[0][1], co[0][2], co[0][3], A0, A1, A2, A3, b0, b1);
            MMA16816(co[1][0], co[1][1], co[1][2], co[1][3], A0, A1, A2, A3, b2, b3);
            MMA16816(co[2][0], co[2][1], co[2][2], co[2][3], A0, A1, A2, A3, b4, b5);
        }
        __syncthreads();
    }

    // Row sums: reduce across the 4 lanes of each quad
    rl0 += __shfl_xor_sync(0xFFFFFFFFu, rl0, 1);
    rl0 += __shfl_xor_sync(0xFFFFFFFFu, rl0, 2);
    rl1 += __shfl_xor_sync(0xFFFFFFFFu, rl1, 1);
    rl1 += __shfl_xor_sync(0xFFFFFFFFu, rl1, 2);

    const int gid = lane >> 2, tig = lane & 3;
    const int r0 = row0 + warp * 16 + gid;
    const int sb = head * KSPLIT + split;

    float* pa = pacc + sb * 24 * NPOS;
#pragma unroll
    for (int nt = 0; nt < 3; nt++) {
        int d = nt * 8 + tig * 2;
        pa[(d) * NPOS + r0]         = co[nt][0];
        pa[(d + 1) * NPOS + r0]     = co[nt][1];
        pa[(d) * NPOS + r0 + 8]     = co[nt][2];
        pa[(d + 1) * NPOS + r0 + 8] = co[nt][3];
    }
    if (tig == 0) {
        pl[sb * NPOS + r0]     = rl0;
        pl[sb * NPOS + r0 + 8] = rl1;
    }
}

// ---------------------------------------------------------------------------
// Combine split-K partials (plain sums — bounded scores).
// ---------------------------------------------------------------------------
__global__ __launch_bounds__(256) void combine_kernel(
    float* __restrict__ out, const float* __restrict__ pacc,
    const float* __restrict__ pl)
{
    const int g = blockIdx.x * 256 + threadIdx.x;   // 32768 = 8 heads * 4096 rows
    const int head = g >> 12, row = g & 4095;
    float l = 0.f;
#pragma unroll
    for (int s = 0; s < KSPLIT; s++)
        l += pl[(head * KSPLIT + s) * NPOS + row];
    const float inv = 1.0f / l;
#pragma unroll
    for (int d = 0; d < 24; d++) {
        float a = 0.f;
#pragma unroll
        for (int s = 0; s < KSPLIT; s++)
            a += pacc[((head * KSPLIT + s) * 24 + d) * NPOS + row];
        out[(head * 24 + d) * NPOS + row] = a * inv;
    }
}

// ---------------------------------------------------------------------------
// Pointwise (1x1) conv fp32 (projection): out[o][p] = sum_c w[o][c]*in[c][p]
// ---------------------------------------------------------------------------
__global__ __launch_bounds__(256) void pw_conv_kernel(
    float* __restrict__ out, const float* __restrict__ in,
    const float* __restrict__ w, int IC)
{
    __shared__ __align__(16) float ws[16][65];
    __shared__ __align__(16) float xs[16][64];

    const int tid = threadIdx.x;
    const int tx = tid & 15, ty = tid >> 4;
    const int p0 = blockIdx.x * 64;
    const int o0 = blockIdx.y * 64;

    float acc[4][4] = {};

    for (int c0 = 0; c0 < IC; c0 += 16) {
        __syncthreads();
#pragma unroll
        for (int i = 0; i < 4; i++) {
            int e = tid + i * 256;
            int oo = e >> 4, ck = e & 15;
            ws[ck][oo] = w[(o0 + oo) * IC + c0 + ck];
        }
#pragma unroll
        for (int i = 0; i < 4; i++) {
            int e = tid + i * 256;
            int ck = e >> 6, pp = e & 63;
            xs[ck][pp] = in[(c0 + ck) * NPOS + p0 + pp];
        }
        __syncthreads();
#pragma unroll
        for (int ck = 0; ck < 16; ck++) {
            float4 xv = *(const float4*)&xs[ck][tx * 4];
            float w0 = ws[ck][ty * 4 + 0];
            float w1 = ws[ck][ty * 4 + 1];
            float w2 = ws[ck][ty * 4 + 2];
            float w3 = ws[ck][ty * 4 + 3];
            acc[0][0] += w0 * xv.x; acc[0][1] += w0 * xv.y; acc[0][2] += w0 * xv.z; acc[0][3] += w0 * xv.w;
            acc[1][0] += w1 * xv.x; acc[1][1] += w1 * xv.y; acc[1][2] += w1 * xv.z; acc[1][3] += w1 * xv.w;
            acc[2][0] += w2 * xv.x; acc[2][1] += w2 * xv.y; acc[2][2] += w2 * xv.z; acc[2][3] += w2 * xv.w;
            acc[3][0] += w3 * xv.x; acc[3][1] += w3 * xv.y; acc[3][2] += w3 * xv.z; acc[3][3] += w3 * xv.w;
        }
    }
#pragma unroll
    for (int i = 0; i < 4; i++)
#pragma unroll
        for (int j = 0; j < 4; j++)
            out[(o0 + ty * 4 + i) * NPOS + p0 + tx * 4 + j] = acc[i][j];
}

// ---------------------------------------------------------------------------
extern "C" void kernel_launch(void* const* d_in, const int* in_sizes, int n_in,
                              void* d_out, int out_size)
{
    const float* x      = (const float*)d_in[0];
    const float* w_qkv  = (const float*)d_in[1];
    const float* w_dw   = (const float*)d_in[2];
    const float* w_proj = (const float*)d_in[3];
    float* out = (float*)d_out;

    float *at, *pa, *plv;
    __half *qkv16, *q16, *k16, *v16;
    cudaGetSymbolAddress((void**)&at, g_attn);
    cudaGetSymbolAddress((void**)&pa, g_pacc);
    cudaGetSymbolAddress((void**)&plv, g_pl);
    cudaGetSymbolAddress((void**)&qkv16, g_qkv16);
    cudaGetSymbolAddress((void**)&q16, g_q16);
    cudaGetSymbolAddress((void**)&k16, g_k16);
    cudaGetSymbolAddress((void**)&v16, g_v16);

    pw1_mma_kernel<<<dim3(NPOS / 64, 576 / 64), 128>>>(qkv16, x, w_qkv);
    dwnorm_kernel<<<384, 256>>>(qkv16, w_dw, q16, k16, v16);
    attn_kernel<<<dim3(NPOS / 64, 8, KSPLIT), 128>>>(pa, plv, q16, k16, v16);
    combine_kernel<<<128, 256>>>(at, pa, plv);
    pw_conv_kernel<<<dim3(NPOS / 64, 192 / 64), 256>>>(out, at, w_proj, 192);
}

// round 10
// speedup vs baseline: 5.7694x; 1.1050x over previous
#include <cuda_runtime.h>
#include <cuda_fp16.h>
#include <math.h>
#include <stdint.h>

#define NPOS 4096
#define QK_SCALE 0.2041241452319315f  /* 24^-0.5 */
#define KSPLIT 2

// Scratch (device globals — no allocation allowed)
__device__ __half g_attn16[192 * NPOS];           // attention output, fp16 [c][p]
__device__ __half g_qkv16[576 * NPOS];            // qkv after 1x1 conv, fp16 [o][p]
__device__ __half g_q16[8 * NPOS * 24];           // normalized q (scale folded), [h][p][d]
__device__ __half g_k16[8 * NPOS * 24];           // normalized k, [h][p][d]
__device__ __half g_v16[8 * NPOS * 24];           // v, [h][p][d]
__device__ float  g_pacc[8 * KSPLIT * 24 * NPOS]; // split-K partial acc
__device__ float  g_pl[8 * KSPLIT * NPOS];        // split-K partial l

__device__ __forceinline__ uint32_t s2u(const void* p){
    uint32_t a;
    asm("{ .reg .u64 t; cvta.to.shared.u64 t, %1; cvt.u32.u64 %0, t; }" : "=r"(a) : "l"(p));
    return a;
}
#define LDSM_X4(r0,r1,r2,r3,a) \
    asm volatile("ldmatrix.sync.aligned.m8n8.x4.shared.b16 {%0,%1,%2,%3}, [%4];" \
        : "=r"(r0), "=r"(r1), "=r"(r2), "=r"(r3) : "r"(a))
#define LDSM_X4T(r0,r1,r2,r3,a) \
    asm volatile("ldmatrix.sync.aligned.m8n8.x4.trans.shared.b16 {%0,%1,%2,%3}, [%4];" \
        : "=r"(r0), "=r"(r1), "=r"(r2), "=r"(r3) : "r"(a))
#define LDSM_X2T(r0,r1,a) \
    asm volatile("ldmatrix.sync.aligned.m8n8.x2.trans.shared.b16 {%0,%1}, [%2];" \
        : "=r"(r0), "=r"(r1) : "r"(a))
#define MMA16816(c0,c1,c2,c3,a0,a1,a2,a3,b0,b1) \
    asm volatile("mma.sync.aligned.m16n8k16.row.col.f32.f16.f16.f32 " \
        "{%0,%1,%2,%3}, {%4,%5,%6,%7}, {%8,%9}, {%0,%1,%2,%3};" \
        : "+f"(c0), "+f"(c1), "+f"(c2), "+f"(c3) \
        : "r"(a0), "r"(a1), "r"(a2), "r"(a3), "r"(b0), "r"(b1))
#define CP16(dst, src) \
    asm volatile("cp.async.cg.shared.global [%0], [%1], 16;" :: "r"(dst), "l"(src))

// exp for |s| <= 0.205 via degree-3 Taylor (rel err < 8e-5); fma pipe.
__device__ __forceinline__ float exp3(float s) {
    float t = fmaf(0.16666667f, s, 0.5f);
    t = fmaf(t, s, 1.0f);
    return fmaf(t, s, 1.0f);
}

// ---------------------------------------------------------------------------
// qkv 1x1 conv via fp16 mma: out16[o][p] = sum_c w[o][c] * x[c][p]  (f32 x)
// CTA: 128 thr / 4 warps, tile O=64 x P=64. Grid: (64, 9).
// ---------------------------------------------------------------------------
__global__ __launch_bounds__(128) void pw1_mma_kernel(
    __half* __restrict__ out16, const float* __restrict__ x,
    const float* __restrict__ w)
{
    __shared__ __align__(16) __half sA[64 * 200];  // [o][k], pad 192->200
    __shared__ __align__(16) __half sB[16 * 72];   // [k16][p64], pad 64->72

    const int tid  = threadIdx.x;
    const int lane = tid & 31, warp = tid >> 5;
    const int p0 = blockIdx.x * 64;
    const int o0 = blockIdx.y * 64;

    {
        const float4* wg = (const float4*)(w + o0 * 192);
#pragma unroll
        for (int i = 0; i < 24; i++) {
            int e = i * 128 + tid;
            int r = e / 48, m = e - 48 * r;
            float4 f = wg[e];
            *(__half2*)(sA + r * 200 + m * 4)     = __floats2half2_rn(f.x, f.y);
            *(__half2*)(sA + r * 200 + m * 4 + 2) = __floats2half2_rn(f.z, f.w);
        }
    }

    float acc[8][4] = {};

    float4 pf[2];
#pragma unroll
    for (int i = 0; i < 2; i++) {
        int e = i * 128 + tid;
        int kk = e >> 4, m = e & 15;
        pf[i] = *(const float4*)(x + kk * NPOS + p0 + m * 4);
    }

    const uint32_t sA_s = s2u(sA), sB_s = s2u(sB);

    for (int ks = 0; ks < 12; ks++) {
        __syncthreads();
#pragma unroll
        for (int i = 0; i < 2; i++) {
            int e = i * 128 + tid;
            int kk = e >> 4, m = e & 15;
            *(__half2*)(sB + kk * 72 + m * 4)     = __floats2half2_rn(pf[i].x, pf[i].y);
            *(__half2*)(sB + kk * 72 + m * 4 + 2) = __floats2half2_rn(pf[i].z, pf[i].w);
        }
        __syncthreads();

        if (ks + 1 < 12) {
#pragma unroll
            for (int i = 0; i < 2; i++) {
                int e = i * 128 + tid;
                int kk = e >> 4, m = e & 15;
                pf[i] = *(const float4*)(x + ((ks + 1) * 16 + kk) * NPOS + p0 + m * 4);
            }
        }

        uint32_t a0, a1, a2, a3;
        LDSM_X4(a0, a1, a2, a3,
                sA_s + (((warp * 16 + (lane & 15)) * 200 + ks * 16 + (lane >> 4) * 8) << 1));
#pragma unroll
        for (int c = 0; c < 4; c++) {
            uint32_t b0, b1, b2, b3;
            LDSM_X4T(b0, b1, b2, b3,
                     sB_s + (((lane & 15) * 72 + c * 16 + (lane >> 4) * 8) << 1));
            MMA16816(acc[2*c][0], acc[2*c][1], acc[2*c][2], acc[2*c][3],
                     a0, a1, a2, a3, b0, b1);
            MMA16816(acc[2*c+1][0], acc[2*c+1][1], acc[2*c+1][2], acc[2*c+1][3],
                     a0, a1, a2, a3, b2, b3);
        }
    }

    const int gid = lane >> 2, tig = lane & 3;
    const int o = o0 + warp * 16 + gid;
#pragma unroll
    for (int c8 = 0; c8 < 8; c8++) {
        int p = p0 + c8 * 8 + tig * 2;
        *(__half2*)&out16[o * NPOS + p]       = __floats2half2_rn(acc[c8][0], acc[c8][1]);
        *(__half2*)&out16[(o + 8) * NPOS + p] = __floats2half2_rn(acc[c8][2], acc[c8][3]);
    }
}

// ---------------------------------------------------------------------------
// proj 1x1 conv via fp16 mma: out[o][p] = sum_c w[o][c] * a16[c][p], f32 out.
// Grid: (64, 3).
// ---------------------------------------------------------------------------
__global__ __launch_bounds__(128) void pw2_mma_kernel(
    float* __restrict__ out, const __half* __restrict__ a16,
    const float* __restrict__ w)
{
    __shared__ __align__(16) __half sA[64 * 200];
    __shared__ __align__(16) __half sB[16 * 72];

    const int tid  = threadIdx.x;
    const int lane = tid & 31, warp = tid >> 5;
    const int p0 = blockIdx.x * 64;
    const int o0 = blockIdx.y * 64;

    {
        const float4* wg = (const float4*)(w + o0 * 192);
#pragma unroll
        for (int i = 0; i < 24; i++) {
            int e = i * 128 + tid;
            int r = e / 48, m = e - 48 * r;
            float4 f = wg[e];
            *(__half2*)(sA + r * 200 + m * 4)     = __floats2half2_rn(f.x, f.y);
            *(__half2*)(sA + r * 200 + m * 4 + 2) = __floats2half2_rn(f.z, f.w);
        }
    }

    float acc[8][4] = {};

    // B prefetch: 16 rows x 64 halfs = 128 uint4; 1 per thread
    uint4 pf = *(const uint4*)(a16 + (tid >> 3) * NPOS + p0 + (tid & 7) * 8);

    const uint32_t sA_s = s2u(sA), sB_s = s2u(sB);

    for (int ks = 0; ks < 12; ks++) {
        __syncthreads();
        *(uint4*)(sB + (tid >> 3) * 72 + (tid & 7) * 8) = pf;
        __syncthreads();

        if (ks + 1 < 12)
            pf = *(const uint4*)(a16 + ((ks + 1) * 16 + (tid >> 3)) * NPOS + p0 + (tid & 7) * 8);

        uint32_t a0, a1, a2, a3;
        LDSM_X4(a0, a1, a2, a3,
                sA_s + (((warp * 16 + (lane & 15)) * 200 + ks * 16 + (lane >> 4) * 8) << 1));
#pragma unroll
        for (int c = 0; c < 4; c++) {
            uint32_t b0, b1, b2, b3;
            LDSM_X4T(b0, b1, b2, b3,
                     sB_s + (((lane & 15) * 72 + c * 16 + (lane >> 4) * 8) << 1));
            MMA16816(acc[2*c][0], acc[2*c][1], acc[2*c][2], acc[2*c][3],
                     a0, a1, a2, a3, b0, b1);
            MMA16816(acc[2*c+1][0], acc[2*c+1][1], acc[2*c+1][2], acc[2*c+1][3],
                     a0, a1, a2, a3, b2, b3);
        }
    }

    const int gid = lane >> 2, tig = lane & 3;
    const int o = o0 + warp * 16 + gid;
#pragma unroll
    for (int c8 = 0; c8 < 8; c8++) {
        int p = p0 + c8 * 8 + tig * 2;
        *(float2*)&out[o * NPOS + p]       = make_float2(acc[c8][0], acc[c8][1]);
        *(float2*)&out[(o + 8) * NPOS + p] = make_float2(acc[c8][2], acc[c8][3]);
    }
}

// ---------------------------------------------------------------------------
// Fused: depthwise 3x3 (padding=1, fp16 input) + L2-normalize (24) + fp16 out.
// ---------------------------------------------------------------------------
__global__ __launch_bounds__(256) void dwnorm_kernel(
    const __half* __restrict__ in, const float* __restrict__ wdw,
    __half* __restrict__ q16, __half* __restrict__ k16, __half* __restrict__ v16)
{
    const int g = blockIdx.x * 256 + threadIdx.x;
    const int t = g >> 15;          // 0=q, 1=k, 2=v
    const int rem = g & 32767;
    const int h = rem >> 12;
    const int p = rem & 4095;
    const int y = p >> 6, x = p & 63;

    const __half* ipb = in + (t * 192 + h * 24) * NPOS;
    const float* wpb = wdw + (t * 192 + h * 24) * 9;

    const bool ym = (y > 0), yp = (y < 63);
    const bool xm = (x > 0), xp = (x < 63);

    float v[24];
    float ss = 0.f;
#pragma unroll
    for (int d = 0; d < 24; d++) {
        const __half* ip = ipb + d * NPOS + p;
        const float* wp = wpb + d * 9;
        float a = wp[4] * __half2float(ip[0]);
        if (ym) {
            a += wp[1] * __half2float(ip[-64]);
            if (xm) a += wp[0] * __half2float(ip[-65]);
            if (xp) a += wp[2] * __half2float(ip[-63]);
        }
        if (xm) a += wp[3] * __half2float(ip[-1]);
        if (xp) a += wp[5] * __half2float(ip[1]);
        if (yp) {
            a += wp[7] * __half2float(ip[64]);
            if (xm) a += wp[6] * __half2float(ip[63]);
            if (xp) a += wp[8] * __half2float(ip[65]);
        }
        v[d] = a;
        ss += a * a;
    }
    float inv;
    if (t == 0)      inv = QK_SCALE / fmaxf(sqrtf(ss), 1e-12f);
    else if (t == 1) inv = 1.0f / fmaxf(sqrtf(ss), 1e-12f);
    else             inv = 1.0f;

    __half* o = (t == 0 ? q16 : (t == 1 ? k16 : v16)) + (h * NPOS + p) * 24;
#pragma unroll
    for (int d = 0; d < 24; d++)
        o[d] = __float2half_rn(v[d] * inv);
}

// ---------------------------------------------------------------------------
// Flash attention via mma.sync m16n8k16, split-K=2, double-buffered cp.async.
// exp split across MUFU (__expf) and fma (Taylor-3) pipes.
// Grid: (64 row tiles, 8 heads, KSPLIT).
// ---------------------------------------------------------------------------
__global__ __launch_bounds__(128) void attn_kernel(
    float* __restrict__ pacc, float* __restrict__ pl,
    const __half* __restrict__ q16, const __half* __restrict__ k16,
    const __half* __restrict__ v16)
{
    __shared__ __align__(16) __half sQ[64 * 40];
    __shared__ __align__(16) __half sK[2][128 * 40];
    __shared__ __align__(16) __half sV[2][128 * 40];

    const int tid   = threadIdx.x;
    const int lane  = tid & 31, warp = tid >> 5;
    const int head  = blockIdx.y;
    const int split = blockIdx.z;
    const int row0  = blockIdx.x * 64;

    uint32_t* sQu = (uint32_t*)sQ;
    uint32_t* sKu = (uint32_t*)sK;

    {
        const uint32_t* qg = (const uint32_t*)(q16 + (head * NPOS + row0) * 24);
#pragma unroll
        for (int i = 0; i < 6; i++) {
            int e = i * 128 + tid;
            int r = e / 12, u = e - 12 * r;
            sQu[r * 20 + u] = qg[e];
        }
#pragma unroll
        for (int i = 0; i < 2; i++) {
            int e = i * 128 + tid;
            int r = e >> 2, u = e & 3;
            sQu[r * 20 + 12 + u] = 0u;
        }
#pragma unroll
        for (int i = 0; i < 8; i++) {
            int e = i * 128 + tid;
            int r = e >> 2, u = e & 3;
            sKu[r * 20 + 12 + u] = 0u;
        }
    }
    __syncthreads();

    uint32_t aq[2][4];
    {
        uint32_t qa = s2u(sQ) + (((warp * 16 + (lane & 15)) * 40 + (lane >> 4) * 8) << 1);
        LDSM_X4(aq[0][0], aq[0][1], aq[0][2], aq[0][3], qa);
        LDSM_X4(aq[1][0], aq[1][1], aq[1][2], aq[1][3], qa + 32);
    }

    float co[3][4] = {};
    float rl0 = 0.f, rl1 = 0.f;

    const uint32_t sK_s = s2u(sK), sV_s = s2u(sV);
    const uint32_t ka0 = sK_s + ((((lane & 7) * 40) + (lane >> 3) * 8) << 1);
    const uint32_t va0 = sV_s + ((((lane & 15) * 40) + (lane >> 4) * 8) << 1);
    const uint32_t va2 = sV_s + ((((lane & 15) * 40) + 16) << 1);

    const uint4* kg4 = (const uint4*)(k16 + head * NPOS * 24);
    const uint4* vg4 = (const uint4*)(v16 + head * NPOS * 24);
    const int tbase = split * (32 / KSPLIT);
    const int NT = 32 / KSPLIT;

    auto stage = [&](int tt, int b) {
        const uint4* kg = kg4 + (tbase + tt) * 384;
        const uint4* vg = vg4 + (tbase + tt) * 384;
        const uint32_t bo = (uint32_t)b * 10240u;
#pragma unroll
        for (int i = 0; i < 3; i++) {
            int e = i * 128 + tid;
            int r = e / 3, m = e - 3 * r;
            uint32_t off = bo + (uint32_t)(r * 80 + m * 16);
            CP16(sK_s + off, kg + e);
            CP16(sV_s + off, vg + e);
        }
        asm volatile("cp.async.commit_group;" ::: "memory");
    };

    stage(0, 0);

    for (int t = 0; t < NT; t++) {
        if (t + 1 < NT) {
            stage(t + 1, (t + 1) & 1);
            asm volatile("cp.async.wait_group 1;" ::: "memory");
        } else {
            asm volatile("cp.async.wait_group 0;" ::: "memory");
        }
        __syncthreads();

        const uint32_t bo = (uint32_t)(t & 1) * 10240u;

        uint32_t ap[16][2];
#pragma unroll
        for (int nt = 0; nt < 16; nt++) {
            uint32_t b0, b1, b2, b3;
            LDSM_X4(b0, b1, b2, b3, ka0 + bo + nt * 640);
            float c0 = 0.f, c1 = 0.f, c2 = 0.f, c3 = 0.f;
            MMA16816(c0, c1, c2, c3, aq[0][0], aq[0][1], aq[0][2], aq[0][3], b0, b1);
            MMA16816(c0, c1, c2, c3, aq[1][0], aq[1][1], aq[1][2], aq[1][3], b2, b3);
            // split exp across MUFU and fma pipes (|s| <= 0.205)
            float p0 = __expf(c0), p1 = exp3(c1);
            float p2 = __expf(c2), p3 = exp3(c3);
            rl0 += p0 + p1;
            rl1 += p2 + p3;
            __half2 h01 = __floats2half2_rn(p0, p1);
            __half2 h23 = __floats2half2_rn(p2, p3);
            ap[nt][0] = *(uint32_t*)&h01;
            ap[nt][1] = *(uint32_t*)&h23;
        }

#pragma unroll
        for (int s = 0; s < 8; s++) {
            uint32_t b0, b1, b2, b3, b4, b5;
            LDSM_X4T(b0, b1, b2, b3, va0 + bo + s * 1280);
            LDSM_X2T(b4, b5, va2 + bo + s * 1280);
            uint32_t A0 = ap[2 * s][0], A1 = ap[2 * s][1];
            uint32_t A2 = ap[2 * s + 1][0], A3 = ap[2 * s + 1][1];
            MMA16816(co[0][0], co[0][1], co[0][2], co[0][3], A0, A1, A2, A3, b0, b1);
            MMA16816(co[1][0], co[1][1], co[1][2], co[1][3], A0, A1, A2, A3, b2, b3);
            MMA16816(co[2][0], co[2][1], co[2][2], co[2][3], A0, A1, A2, A3, b4, b5);
        }
        __syncthreads();
    }

    rl0 += __shfl_xor_sync(0xFFFFFFFFu, rl0, 1);
    rl0 += __shfl_xor_sync(0xFFFFFFFFu, rl0, 2);
    rl1 += __shfl_xor_sync(0xFFFFFFFFu, rl1, 1);
    rl1 += __shfl_xor_sync(0xFFFFFFFFu, rl1, 2);

    const int gid = lane >> 2, tig = lane & 3;
    const int r0 = row0 + warp * 16 + gid;
    const int sb = head * KSPLIT + split;

    float* pa = pacc + sb * 24 * NPOS;
#pragma unroll
    for (int nt = 0; nt < 3; nt++) {
        int d = nt * 8 + tig * 2;
        pa[(d) * NPOS + r0]         = co[nt][0];
        pa[(d + 1) * NPOS + r0]     = co[nt][1];
        pa[(d) * NPOS + r0 + 8]     = co[nt][2];
        pa[(d + 1) * NPOS + r0 + 8] = co[nt][3];
    }
    if (tig == 0) {
        pl[sb * NPOS + r0]     = rl0;
        pl[sb * NPOS + r0 + 8] = rl1;
    }
}

// ---------------------------------------------------------------------------
// Combine split-K partials -> fp16 [c][p] for the fp16 proj GEMM.
// ---------------------------------------------------------------------------
__global__ __launch_bounds__(256) void combine_kernel(
    __half* __restrict__ out16, const float* __restrict__ pacc,
    const float* __restrict__ pl)
{
    const int g = blockIdx.x * 256 + threadIdx.x;   // 32768
    const int head = g >> 12, row = g & 4095;
    float l = 0.f;
#pragma unroll
    for (int s = 0; s < KSPLIT; s++)
        l += pl[(head * KSPLIT + s) * NPOS + row];
    const float inv = 1.0f / l;
#pragma unroll
    for (int d = 0; d < 24; d++) {
        float a = 0.f;
#pragma unroll
        for (int s = 0; s < KSPLIT; s++)
            a += pacc[((head * KSPLIT + s) * 24 + d) * NPOS + row];
        out16[(head * 24 + d) * NPOS + row] = __float2half_rn(a * inv);
    }
}

// ---------------------------------------------------------------------------
extern "C" void kernel_launch(void* const* d_in, const int* in_sizes, int n_in,
                              void* d_out, int out_size)
{
    const float* x      = (const float*)d_in[0];
    const float* w_qkv  = (const float*)d_in[1];
    const float* w_dw   = (const float*)d_in[2];
    const float* w_proj = (const float*)d_in[3];
    float* out = (float*)d_out;

    float *pa, *plv;
    __half *at16, *qkv16, *q16, *k16, *v16;
    cudaGetSymbolAddress((void**)&at16, g_attn16);
    cudaGetSymbolAddress((void**)&pa, g_pacc);
    cudaGetSymbolAddress((void**)&plv, g_pl);
    cudaGetSymbolAddress((void**)&qkv16, g_qkv16);
    cudaGetSymbolAddress((void**)&q16, g_q16);
    cudaGetSymbolAddress((void**)&k16, g_k16);
    cudaGetSymbolAddress((void**)&v16, g_v16);

    pw1_mma_kernel<<<dim3(NPOS / 64, 576 / 64), 128>>>(qkv16, x, w_qkv);
    dwnorm_kernel<<<384, 256>>>(qkv16, w_dw, q16, k16, v16);
    attn_kernel<<<dim3(NPOS / 64, 8, KSPLIT), 128>>>(pa, plv, q16, k16, v16);
    combine_kernel<<<128, 256>>>(at16, pa, plv);
    pw2_mma_kernel<<<dim3(NPOS / 64, 192 / 64), 128>>>(out, at16, w_proj);
}

// round 13
// speedup vs baseline: 5.8048x; 1.0061x over previous
#include <cuda_runtime.h>
#include <cuda_fp16.h>
#include <math.h>
#include <stdint.h>

#define NPOS 4096
#define QK_SCALE 0.2041241452319315f  /* 24^-0.5 */
#define KSPLIT 2

// Scratch (device globals — no allocation allowed)
__device__ __half g_qkv16[576 * NPOS];            // qkv after 1x1 conv, fp16 [o][p]
__device__ __half g_q16[8 * NPOS * 24];           // normalized q (scale folded), [h][p][d]
__device__ __half g_k16[8 * NPOS * 24];           // normalized k, [h][p][d]
__device__ __half g_v16[8 * NPOS * 24];           // v, [h][p][d]
__device__ float  g_pacc[8 * KSPLIT * 24 * NPOS]; // split-K partial acc
__device__ float  g_pl[8 * KSPLIT * NPOS];        // split-K partial l

__device__ __forceinline__ uint32_t s2u(const void* p){
    uint32_t a;
    asm("{ .reg .u64 t; cvta.to.shared.u64 t, %1; cvt.u32.u64 %0, t; }" : "=r"(a) : "l"(p));
    return a;
}
#define LDSM_X4(r0,r1,r2,r3,a) \
    asm volatile("ldmatrix.sync.aligned.m8n8.x4.shared.b16 {%0,%1,%2,%3}, [%4];" \
        : "=r"(r0), "=r"(r1), "=r"(r2), "=r"(r3) : "r"(a))
#define LDSM_X4T(r0,r1,r2,r3,a) \
    asm volatile("ldmatrix.sync.aligned.m8n8.x4.trans.shared.b16 {%0,%1,%2,%3}, [%4];" \
        : "=r"(r0), "=r"(r1), "=r"(r2), "=r"(r3) : "r"(a))
#define LDSM_X2T(r0,r1,a) \
    asm volatile("ldmatrix.sync.aligned.m8n8.x2.trans.shared.b16 {%0,%1}, [%2];" \
        : "=r"(r0), "=r"(r1) : "r"(a))
#define MMA16816(c0,c1,c2,c3,a0,a1,a2,a3,b0,b1) \
    asm volatile("mma.sync.aligned.m16n8k16.row.col.f32.f16.f16.f32 " \
        "{%0,%1,%2,%3}, {%4,%5,%6,%7}, {%8,%9}, {%0,%1,%2,%3};" \
        : "+f"(c0), "+f"(c1), "+f"(c2), "+f"(c3) \
        : "r"(a0), "r"(a1), "r"(a2), "r"(a3), "r"(b0), "r"(b1))
#define CP16(dst, src) \
    asm volatile("cp.async.cg.shared.global [%0], [%1], 16;" :: "r"(dst), "l"(src))

// exp for |s| <= 0.205 via degree-3 Taylor (rel err < 8e-5); fma pipe.
__device__ __forceinline__ float exp3(float s) {
    float t = fmaf(0.16666667f, s, 0.5f);
    t = fmaf(t, s, 1.0f);
    return fmaf(t, s, 1.0f);
}

// ---------------------------------------------------------------------------
// qkv 1x1 conv via fp16 mma: out16[o][p] = sum_c w[o][c] * x[c][p]  (f32 x)
// CTA: 128 thr / 4 warps, tile O=64 x P=64. Grid: (64, 9).
// ---------------------------------------------------------------------------
__global__ __launch_bounds__(128) void pw1_mma_kernel(
    __half* __restrict__ out16, const float* __restrict__ x,
    const float* __restrict__ w)
{
    __shared__ __align__(16) __half sA[64 * 200];  // [o][k], pad 192->200
    __shared__ __align__(16) __half sB[16 * 72];   // [k16][p64], pad 64->72

    const int tid  = threadIdx.x;
    const int lane = tid & 31, warp = tid >> 5;
    const int p0 = blockIdx.x * 64;
    const int o0 = blockIdx.y * 64;

    {
        const float4* wg = (const float4*)(w + o0 * 192);
#pragma unroll
        for (int i = 0; i < 24; i++) {
            int e = i * 128 + tid;
            int r = e / 48, m = e - 48 * r;
            float4 f = wg[e];
            *(__half2*)(sA + r * 200 + m * 4)     = __floats2half2_rn(f.x, f.y);
            *(__half2*)(sA + r * 200 + m * 4 + 2) = __floats2half2_rn(f.z, f.w);
        }
    }

    float acc[8][4] = {};

    float4 pf[2];
#pragma unroll
    for (int i = 0; i < 2; i++) {
        int e = i * 128 + tid;
        int kk = e >> 4, m = e & 15;
        pf[i] = *(const float4*)(x + kk * NPOS + p0 + m * 4);
    }

    const uint32_t sA_s = s2u(sA), sB_s = s2u(sB);

    for (int ks = 0; ks < 12; ks++) {
        __syncthreads();
#pragma unroll
        for (int i = 0; i < 2; i++) {
            int e = i * 128 + tid;
            int kk = e >> 4, m = e & 15;
            *(__half2*)(sB + kk * 72 + m * 4)     = __floats2half2_rn(pf[i].x, pf[i].y);
            *(__half2*)(sB + kk * 72 + m * 4 + 2) = __floats2half2_rn(pf[i].z, pf[i].w);
        }
        __syncthreads();

        if (ks + 1 < 12) {
#pragma unroll
            for (int i = 0; i < 2; i++) {
                int e = i * 128 + tid;
                int kk = e >> 4, m = e & 15;
                pf[i] = *(const float4*)(x + ((ks + 1) * 16 + kk) * NPOS + p0 + m * 4);
            }
        }

        uint32_t a0, a1, a2, a3;
        LDSM_X4(a0, a1, a2, a3,
                sA_s + (((warp * 16 + (lane & 15)) * 200 + ks * 16 + (lane >> 4) * 8) << 1));
#pragma unroll
        for (int c = 0; c < 4; c++) {
            uint32_t b0, b1, b2, b3;
            LDSM_X4T(b0, b1, b2, b3,
                     sB_s + (((lane & 15) * 72 + c * 16 + (lane >> 4) * 8) << 1));
            MMA16816(acc[2*c][0], acc[2*c][1], acc[2*c][2], acc[2*c][3],
                     a0, a1, a2, a3, b0, b1);
            MMA16816(acc[2*c+1][0], acc[2*c+1][1], acc[2*c+1][2], acc[2*c+1][3],
                     a0, a1, a2, a3, b2, b3);
        }
    }

    const int gid = lane >> 2, tig = lane & 3;
    const int o = o0 + warp * 16 + gid;
#pragma unroll
    for (int c8 = 0; c8 < 8; c8++) {
        int p = p0 + c8 * 8 + tig * 2;
        *(__half2*)&out16[o * NPOS + p]       = __floats2half2_rn(acc[c8][0], acc[c8][1]);
        *(__half2*)&out16[(o + 8) * NPOS + p] = __floats2half2_rn(acc[c8][2], acc[c8][3]);
    }
}

// ---------------------------------------------------------------------------
// proj 1x1 conv via fp16 mma with FUSED split-K combine:
//   a16[c][p] = (pacc_s0[c][p] + pacc_s1[c][p]) / (l0[h][p] + l1[h][p]),
// computed inline while staging B. Grid: (64, 3). f32 out.
// ---------------------------------------------------------------------------
__global__ __launch_bounds__(128) void pw2_mma_kernel(
    float* __restrict__ out, const float* __restrict__ pacc,
    const float* __restrict__ pl, const float* __restrict__ w)
{
    __shared__ __align__(16) __half sA[64 * 200];
    __shared__ __align__(16) __half sB[16 * 72];
    __shared__ __align__(16) float  sLinv[512];   // [head 8][p 64]

    const int tid  = threadIdx.x;
    const int lane = tid & 31, warp = tid >> 5;
    const int p0 = blockIdx.x * 64;
    const int o0 = blockIdx.y * 64;

    {
        const float4* wg = (const float4*)(w + o0 * 192);
#pragma unroll
        for (int i = 0; i < 24; i++) {
            int e = i * 128 + tid;
            int r = e / 48, m = e - 48 * r;
            float4 f = wg[e];
            *(__half2*)(sA + r * 200 + m * 4)     = __floats2half2_rn(f.x, f.y);
            *(__half2*)(sA + r * 200 + m * 4 + 2) = __floats2half2_rn(f.z, f.w);
        }
    }
    // linv table: 8 heads x 64 positions
#pragma unroll
    for (int i = 0; i < 4; i++) {
        int idx = i * 128 + tid;
        int h = idx >> 6, pp = idx & 63;
        float l = pl[(h * 2) * NPOS + p0 + pp] + pl[(h * 2 + 1) * NPOS + p0 + pp];
        sLinv[idx] = 1.0f / l;
    }

    float acc[8][4] = {};

    const int br = tid >> 3;            // B row 0..15
    const int m8 = (tid & 7) * 8;       // p offset 0..56

    float4 pa0, pa1, pb0, pb1;
    auto loadB = [&](int ks) {
        int c = ks * 16 + br;
        int h = (c * 21846) >> 19;      // c / 24
        int d = c - h * 24;
        const float* s0 = pacc + ((h * 2) * 24 + d) * NPOS + p0 + m8;
        const float* s1 = s0 + 24 * NPOS;
        pa0 = *(const float4*)s0;  pb0 = *(const float4*)(s0 + 4);
        pa1 = *(const float4*)s1;  pb1 = *(const float4*)(s1 + 4);
    };
    loadB(0);

    const uint32_t sA_s = s2u(sA), sB_s = s2u(sB);

    for (int ks = 0; ks < 12; ks++) {
        __syncthreads();   // orders sLinv writes (ks=0) and protects sB reuse
        {
            int c = ks * 16 + br;
            int h = (c * 21846) >> 19;
            const float* li = sLinv + h * 64 + m8;
            float4 l0 = *(const float4*)li, l1 = *(const float4*)(li + 4);
            float v0 = (pa0.x + pa1.x) * l0.x;
            float v1 = (pa0.y + pa1.y) * l0.y;
            float v2 = (pa0.z + pa1.z) * l0.z;
            float v3 = (pa0.w + pa1.w) * l0.w;
            float v4 = (pb0.x + pb1.x) * l1.x;
            float v5 = (pb0.y + pb1.y) * l1.y;
            float v6 = (pb0.z + pb1.z) * l1.z;
            float v7 = (pb0.w + pb1.w) * l1.w;
            __half* d8 = sB + br * 72 + m8;
            *(__half2*)(d8)     = __floats2half2_rn(v0, v1);
            *(__half2*)(d8 + 2) = __floats2half2_rn(v2, v3);
            *(__half2*)(d8 + 4) = __floats2half2_rn(v4, v5);
            *(__half2*)(d8 + 6) = __floats2half2_rn(v6, v7);
        }
        __syncthreads();

        if (ks + 1 < 12) loadB(ks + 1);

        uint32_t a0, a1, a2, a3;
        LDSM_X4(a0, a1, a2, a3,
                sA_s + (((warp * 16 + (lane & 15)) * 200 + ks * 16 + (lane >> 4) * 8) << 1));
#pragma unroll
        for (int c = 0; c < 4; c++) {
            uint32_t b0, b1, b2, b3;
            LDSM_X4T(b0, b1, b2, b3,
                     sB_s + (((lane & 15) * 72 + c * 16 + (lane >> 4) * 8) << 1));
            MMA16816(acc[2*c][0], acc[2*c][1], acc[2*c][2], acc[2*c][3],
                     a0, a1, a2, a3, b0, b1);
            MMA16816(acc[2*c+1][0], acc[2*c+1][1], acc[2*c+1][2], acc[2*c+1][3],
                     a0, a1, a2, a3, b2, b3);
        }
    }

    const int gid = lane >> 2, tig = lane & 3;
    const int o = o0 + warp * 16 + gid;
#pragma unroll
    for (int c8 = 0; c8 < 8; c8++) {
        int p = p0 + c8 * 8 + tig * 2;
        *(float2*)&out[o * NPOS + p]       = make_float2(acc[c8][0], acc[c8][1]);
        *(float2*)&out[(o + 8) * NPOS + p] = make_float2(acc[c8][2], acc[c8][3]);
    }
}

// ---------------------------------------------------------------------------
// Fused: depthwise 3x3 (padding=1, fp16 input) + L2-normalize (24) + fp16 out.
// ---------------------------------------------------------------------------
__global__ __launch_bounds__(256) void dwnorm_kernel(
    const __half* __restrict__ in, const float* __restrict__ wdw,
    __half* __restrict__ q16, __half* __restrict__ k16, __half* __restrict__ v16)
{
    const int g = blockIdx.x * 256 + threadIdx.x;
    const int t = g >> 15;          // 0=q, 1=k, 2=v
    const int rem = g & 32767;
    const int h = rem >> 12;
    const int p = rem & 4095;
    const int y = p >> 6, x = p & 63;

    const __half* ipb = in + (t * 192 + h * 24) * NPOS;
    const float* wpb = wdw + (t * 192 + h * 24) * 9;

    const bool ym = (y > 0), yp = (y < 63);
    const bool xm = (x > 0), xp = (x < 63);

    float v[24];
    float ss = 0.f;
#pragma unroll
    for (int d = 0; d < 24; d++) {
        const __half* ip = ipb + d * NPOS + p;
        const float* wp = wpb + d * 9;
        float a = wp[4] * __half2float(ip[0]);
        if (ym) {
            a += wp[1] * __half2float(ip[-64]);
            if (xm) a += wp[0] * __half2float(ip[-65]);
            if (xp) a += wp[2] * __half2float(ip[-63]);
        }
        if (xm) a += wp[3] * __half2float(ip[-1]);
        if (xp) a += wp[5] * __half2float(ip[1]);
        if (yp) {
            a += wp[7] * __half2float(ip[64]);
            if (xm) a += wp[6] * __half2float(ip[63]);
            if (xp) a += wp[8] * __half2float(ip[65]);
        }
        v[d] = a;
        ss += a * a;
    }
    float inv;
    if (t == 0)      inv = QK_SCALE / fmaxf(sqrtf(ss), 1e-12f);
    else if (t == 1) inv = 1.0f / fmaxf(sqrtf(ss), 1e-12f);
    else             inv = 1.0f;

    __half* o = (t == 0 ? q16 : (t == 1 ? k16 : v16)) + (h * NPOS + p) * 24;
#pragma unroll
    for (int d = 0; d < 24; d++)
        o[d] = __float2half_rn(v[d] * inv);
}

// ---------------------------------------------------------------------------
// Flash attention via mma.sync m16n8k16, split-K=2, double-buffered cp.async.
// All exps via degree-3 Taylor on the fma pipe (scores bounded ±0.205).
// Grid: (64 row tiles, 8 heads, KSPLIT).
// ---------------------------------------------------------------------------
__global__ __launch_bounds__(128) void attn_kernel(
    float* __restrict__ pacc, float* __restrict__ pl,
    const __half* __restrict__ q16, const __half* __restrict__ k16,
    const __half* __restrict__ v16)
{
    __shared__ __align__(16) __half sQ[64 * 40];
    __shared__ __align__(16) __half sK[2][128 * 40];
    __shared__ __align__(16) __half sV[2][128 * 40];

    const int tid   = threadIdx.x;
    const int lane  = tid & 31, warp = tid >> 5;
    const int head  = blockIdx.y;
    const int split = blockIdx.z;
    const int row0  = blockIdx.x * 64;

    uint32_t* sQu = (uint32_t*)sQ;
    uint32_t* sKu = (uint32_t*)sK;

    {
        const uint32_t* qg = (const uint32_t*)(q16 + (head * NPOS + row0) * 24);
#pragma unroll
        for (int i = 0; i < 6; i++) {
            int e = i * 128 + tid;
            int r = e / 12, u = e - 12 * r;
            sQu[r * 20 + u] = qg[e];
        }
#pragma unroll
        for (int i = 0; i < 2; i++) {
            int e = i * 128 + tid;
            int r = e >> 2, u = e & 3;
            sQu[r * 20 + 12 + u] = 0u;
        }
#pragma unroll
        for (int i = 0; i < 8; i++) {
            int e = i * 128 + tid;
            int r = e >> 2, u = e & 3;
            sKu[r * 20 + 12 + u] = 0u;
        }
    }
    __syncthreads();

    uint32_t aq[2][4];
    {
        uint32_t qa = s2u(sQ) + (((warp * 16 + (lane & 15)) * 40 + (lane >> 4) * 8) << 1);
        LDSM_X4(aq[0][0], aq[0][1], aq[0][2], aq[0][3], qa);
        LDSM_X4(aq[1][0], aq[1][1], aq[1][2], aq[1][3], qa + 32);
    }

    float co[3][4] = {};
    float rl0 = 0.f, rl1 = 0.f;

    const uint32_t sK_s = s2u(sK), sV_s = s2u(sV);
    const uint32_t ka0 = sK_s + ((((lane & 7) * 40) + (lane >> 3) * 8) << 1);
    const uint32_t va0 = sV_s + ((((lane & 15) * 40) + (lane >> 4) * 8) << 1);
    const uint32_t va2 = sV_s + ((((lane & 15) * 40) + 16) << 1);

    const uint4* kg4 = (const uint4*)(k16 + head * NPOS * 24);
    const uint4* vg4 = (const uint4*)(v16 + head * NPOS * 24);
    const int tbase = split * (32 / KSPLIT);
    const int NT = 32 / KSPLIT;

    auto stage = [&](int tt, int b) {
        const uint4* kg = kg4 + (tbase + tt) * 384;
        const uint4* vg = vg4 + (tbase + tt) * 384;
        const uint32_t bo = (uint32_t)b * 10240u;
#pragma unroll
        for (int i = 0; i < 3; i++) {
            int e = i * 128 + tid;
            int r = e / 3, m = e - 3 * r;
            uint32_t off = bo + (uint32_t)(r * 80 + m * 16);
            CP16(sK_s + off, kg + e);
            CP16(sV_s + off, vg + e);
        }
        asm volatile("cp.async.commit_group;" ::: "memory");
    };

    stage(0, 0);

    for (int t = 0; t < NT; t++) {
        if (t + 1 < NT) {
            stage(t + 1, (t + 1) & 1);
            asm volatile("cp.async.wait_group 1;" ::: "memory");
        } else {
            asm volatile("cp.async.wait_group 0;" ::: "memory");
        }
        __syncthreads();

        const uint32_t bo = (uint32_t)(t & 1) * 10240u;

        uint32_t ap[16][2];
#pragma unroll
        for (int nt = 0; nt < 16; nt++) {
            uint32_t b0, b1, b2, b3;
            LDSM_X4(b0, b1, b2, b3, ka0 + bo + nt * 640);
            float c0 = 0.f, c1 = 0.f, c2 = 0.f, c3 = 0.f;
            MMA16816(c0, c1, c2, c3, aq[0][0], aq[0][1], aq[0][2], aq[0][3], b0, b1);
            MMA16816(c0, c1, c2, c3, aq[1][0], aq[1][1], aq[1][2], aq[1][3], b2, b3);
            float p0 = exp3(c0), p1 = exp3(c1);
            float p2 = exp3(c2), p3 = exp3(c3);
            rl0 += p0 + p1;
            rl1 += p2 + p3;
            __half2 h01 = __floats2half2_rn(p0, p1);
            __half2 h23 = __floats2half2_rn(p2, p3);
            ap[nt][0] = *(uint32_t*)&h01;
            ap[nt][1] = *(uint32_t*)&h23;
        }

#pragma unroll
        for (int s = 0; s < 8; s++) {
            uint32_t b0, b1, b2, b3, b4, b5;
            LDSM_X4T(b0, b1, b2, b3, va0 + bo + s * 1280);
            LDSM_X2T(b4, b5, va2 + bo + s * 1280);
            uint32_t A0 = ap[2 * s][0], A1 = ap[2 * s][1];
            uint32_t A2 = ap[2 * s + 1][0], A3 = ap[2 * s + 1][1];
            MMA16816(co[0][0], co[0][1], co[0][2], co[0][3], A0, A1, A2, A3, b0, b1);
            MMA16816(co[1][0], co[1][1], co[1][2], co[1][3], A0, A1, A2, A3, b2, b3);
            MMA16816(co[2][0], co[2][1], co[2][2], co[2][3], A0, A1, A2, A3, b4, b5);
        }
        __syncthreads();
    }

    rl0 += __shfl_xor_sync(0xFFFFFFFFu, rl0, 1);
    rl0 += __shfl_xor_sync(0xFFFFFFFFu, rl0, 2);
    rl1 += __shfl_xor_sync(0xFFFFFFFFu, rl1, 1);
    rl1 += __shfl_xor_sync(0xFFFFFFFFu, rl1, 2);

    const int gid = lane >> 2, tig = lane & 3;
    const int r0 = row0 + warp * 16 + gid;
    const int sb = head * KSPLIT + split;

    float* pa = pacc + sb * 24 * NPOS;
#pragma unroll
    for (int nt = 0; nt < 3; nt++) {
        int d = nt * 8 + tig * 2;
        pa[(d) * NPOS + r0]         = co[nt][0];
        pa[(d + 1) * NPOS + r0]     = co[nt][1];
        pa[(d) * NPOS + r0 + 8]     = co[nt][2];
        pa[(d + 1) * NPOS + r0 + 8] = co[nt][3];
    }
    if (tig == 0) {
        pl[sb * NPOS + r0]     = rl0;
        pl[sb * NPOS + r0 + 8] = rl1;
    }
}

// ---------------------------------------------------------------------------
extern "C" void kernel_launch(void* const* d_in, const int* in_sizes, int n_in,
                              void* d_out, int out_size)
{
    const float* x      = (const float*)d_in[0];
    const float* w_qkv  = (const float*)d_in[1];
    const float* w_dw   = (const float*)d_in[2];
    const float* w_proj = (const float*)d_in[3];
    float* out = (float*)d_out;

    float *pa, *plv;
    __half *qkv16, *q16, *k16, *v16;
    cudaGetSymbolAddress((void**)&pa, g_pacc);
    cudaGetSymbolAddress((void**)&plv, g_pl);
    cudaGetSymbolAddress((void**)&qkv16, g_qkv16);
    cudaGetSymbolAddress((void**)&q16, g_q16);
    cudaGetSymbolAddress((void**)&k16, g_k16);
    cudaGetSymbolAddress((void**)&v16, g_v16);

    pw1_mma_kernel<<<dim3(NPOS / 64, 576 / 64), 128>>>(qkv16, x, w_qkv);
    dwnorm_kernel<<<384, 256>>>(qkv16, w_dw, q16, k16, v16);
    attn_kernel<<<dim3(NPOS / 64, 8, KSPLIT), 128>>>(pa, plv, q16, k16, v16);
    pw2_mma_kernel<<<dim3(NPOS / 64, 192 / 64), 128>>>(out, pa, plv, w_proj);
}